// round 12
// baseline (speedup 1.0000x reference)
#include <cuda_runtime.h>
#include <cuda_fp16.h>
#include <math.h>
#include <stdint.h>

// ---------------- problem constants ----------------
#define BATCH 2
#define SEQ 1024
#define HIDDEN 2048
#define HQ 32
#define HKV 8
#define HD 64
#define MROWS (BATCH * SEQ)     // 2048
#define KDIM HIDDEN             // 2048
#define NQKV 3072               // fused q(2048) | k(512) | v(512)
#define NEG_BIG (-1e9f)

// ---------------- scratch ----------------
__device__ float g_qkv[MROWS * NQKV];

__device__ __half gA_hi[MROWS * KDIM];
__device__ __half gA_lo[MROWS * KDIM];
__device__ __half gBqkv[NQKV * KDIM];
__device__ __half gBo[2048 * KDIM];

__device__ __half gQhi[MROWS * HQ * HD];
__device__ __half gQlo[MROWS * HQ * HD];
__device__ __half gKhi[MROWS * HKV * HD];
__device__ __half gVThi[BATCH * HKV * HD * SEQ];
__device__ __half gVTlo[BATCH * HKV * HD * SEQ];

// ---------------- helpers ----------------
__device__ __forceinline__ uint32_t smem_to_u32(const void* p) {
    uint32_t a;
    asm("{ .reg .u64 t; cvta.to.shared.u64 t, %1; cvt.u32.u64 %0, t; }" : "=r"(a) : "l"(p));
    return a;
}
#define LDM4(r0, r1, r2, r3, addr) \
    asm volatile("ldmatrix.sync.aligned.m8n8.x4.shared.b16 {%0,%1,%2,%3}, [%4];" \
        : "=r"(r0), "=r"(r1), "=r"(r2), "=r"(r3) : "r"(addr))

__device__ __forceinline__ void mma16816(float* d, const uint32_t* a, uint32_t b0, uint32_t b1) {
    asm volatile("mma.sync.aligned.m16n8k16.row.col.f32.f16.f16.f32 "
        "{%0,%1,%2,%3}, {%4,%5,%6,%7}, {%8,%9}, {%0,%1,%2,%3};"
        : "+f"(d[0]), "+f"(d[1]), "+f"(d[2]), "+f"(d[3])
        : "r"(a[0]), "r"(a[1]), "r"(a[2]), "r"(a[3]), "r"(b0), "r"(b1));
}
__device__ __forceinline__ uint32_t pack_f16x2(float lo, float hi) {
    uint32_t d;
    asm("cvt.rn.f16x2.f32 %0, %1, %2;" : "=r"(d) : "f"(hi), "f"(lo));
    return d;
}

// ---------------- fp16x2 GEMM (R9 config): 64x128 tile, BK=32, 3 stages, occ 3 ----------------
#define BK 32
#define PITCH 40
#define A_ELEMS (64 * PITCH)                        // 2560
#define B_ELEMS (128 * PITCH)                       // 5120
#define STAGE_ELEMS (2 * A_ELEMS + B_ELEMS)         // 10240 elems = 20480 B
#define NSTAGE 3
#define GEMM_SMEM (NSTAGE * STAGE_ELEMS * 2)        // 61440 bytes
#define NCHUNK (KDIM / BK)                          // 64

__device__ __forceinline__ void issue_stage(
    uint32_t sb, int stage,
    const __half* __restrict__ Ahi, const __half* __restrict__ Alo,
    const __half* __restrict__ B,
    int m0, int n0, int k0, int tid)
{
    #pragma unroll
    for (int t = 0; t < 8; t++) {
        int idx = tid + t * 128;            // 0..1023
        int ch = idx & 3;
        const __half* src;
        uint32_t dstoff;
        if (idx < 512) {
            int tl = idx >> 8;
            int row = (idx >> 2) & 63;
            src = (tl ? Alo : Ahi) + (size_t)(m0 + row) * KDIM + k0 + ch * 8;
            dstoff = (uint32_t)(tl * A_ELEMS + row * PITCH + ch * 8);
        } else {
            int row = (idx >> 2) & 127;
            src = B + (size_t)(n0 + row) * KDIM + k0 + ch * 8;
            dstoff = (uint32_t)(2 * A_ELEMS + row * PITCH + ch * 8);
        }
        uint32_t dst = sb + 2u * ((uint32_t)stage * STAGE_ELEMS + dstoff);
        asm volatile("cp.async.cg.shared.global [%0], [%1], 16;" :: "r"(dst), "l"(src));
    }
    asm volatile("cp.async.commit_group;");
}

__global__ __launch_bounds__(128, 3) void gemm_fp16x2_kernel(
    const __half* __restrict__ Ahi, const __half* __restrict__ Alo,
    const __half* __restrict__ B,
    float* __restrict__ C, int N)
{
    extern __shared__ char smem[];
    const uint32_t sb = smem_to_u32(smem);
    const int tid = threadIdx.x;
    const int wid = tid >> 5;
    const int lid = tid & 31;
    const int g = lid >> 2;
    const int t4 = lid & 3;
    const int n0 = blockIdx.x * 128;
    const int m0 = blockIdx.y * 64;

    const int arow_l = (lid & 7) + ((lid >> 3) & 1) * 8;
    const int acol_l = (lid >> 4) * 8;
    const int brow_l = (lid & 7) + (lid >> 4) * 8;
    const int bcol_l = ((lid >> 3) & 1) * 8;

    float acc[4][4][4];
    #pragma unroll
    for (int i = 0; i < 4; i++)
        #pragma unroll
        for (int j = 0; j < 4; j++)
            #pragma unroll
            for (int r = 0; r < 4; r++) acc[i][j][r] = 0.f;

    issue_stage(sb, 0, Ahi, Alo, B, m0, n0, 0, tid);
    issue_stage(sb, 1, Ahi, Alo, B, m0, n0, BK, tid);

    int p = 0;
    for (int i = 0; i < NCHUNK; i++) {
        if (i < NCHUNK - 1) {
            asm volatile("cp.async.wait_group 1;" ::: "memory");
        } else {
            asm volatile("cp.async.wait_group 0;" ::: "memory");
        }
        __syncthreads();

        if (i + 2 < NCHUNK) {
            int st = p + 2; if (st >= NSTAGE) st -= NSTAGE;
            issue_stage(sb, st, Ahi, Alo, B, m0, n0, (i + 2) * BK, tid);
        }

        const uint32_t base = sb + 2u * (uint32_t)(p * STAGE_ELEMS);
        #pragma unroll
        for (int ks = 0; ks < 2; ks++) {
            const int kb = ks * 16;
            uint32_t ah[4][4], al[4][4], bb[4][2];
            #pragma unroll
            for (int mt = 0; mt < 4; mt++) {
                uint32_t ad = base + 2u * (uint32_t)((mt * 16 + arow_l) * PITCH + kb + acol_l);
                LDM4(ah[mt][0], ah[mt][1], ah[mt][2], ah[mt][3], ad);
                LDM4(al[mt][0], al[mt][1], al[mt][2], al[mt][3], ad + 2u * A_ELEMS);
            }
            #pragma unroll
            for (int ntp = 0; ntp < 2; ntp++) {
                uint32_t bd = base + 2u * (uint32_t)(2 * A_ELEMS + (wid * 32 + ntp * 16 + brow_l) * PITCH + kb + bcol_l);
                uint32_t r0, r1, r2, r3;
                LDM4(r0, r1, r2, r3, bd);
                bb[2 * ntp][0] = r0; bb[2 * ntp][1] = r1;
                bb[2 * ntp + 1][0] = r2; bb[2 * ntp + 1][1] = r3;
            }
            #pragma unroll
            for (int mt = 0; mt < 4; mt++)
                #pragma unroll
                for (int nt = 0; nt < 4; nt++)
                    mma16816(acc[mt][nt], ah[mt], bb[nt][0], bb[nt][1]);
            #pragma unroll
            for (int mt = 0; mt < 4; mt++)
                #pragma unroll
                for (int nt = 0; nt < 4; nt++)
                    mma16816(acc[mt][nt], al[mt], bb[nt][0], bb[nt][1]);
        }
        if (++p == NSTAGE) p = 0;
    }

    #pragma unroll
    for (int mt = 0; mt < 4; mt++) {
        int row = m0 + mt * 16 + g;
        #pragma unroll
        for (int nt = 0; nt < 4; nt++) {
            int col = n0 + wid * 32 + nt * 8 + 2 * t4;
            *(float2*)&C[(size_t)row * N + col] = make_float2(acc[mt][nt][0], acc[mt][nt][1]);
            *(float2*)&C[(size_t)(row + 8) * N + col] = make_float2(acc[mt][nt][2], acc[mt][nt][3]);
        }
    }
}

// ---------------- fused input prep: activation split + ALL weight transposes ----------------
#define ISPLIT_BLKS 4096
#define WT_BLKS (160 * 64)
#define IN_TOTAL_BLKS (ISPLIT_BLKS + WT_BLKS)

__global__ void input_prep_kernel(const float* __restrict__ hidden,
                                  const float* __restrict__ Wq, const float* __restrict__ Wk,
                                  const float* __restrict__ Wv, const float* __restrict__ Wo,
                                  __half* __restrict__ aHi, __half* __restrict__ aLo,
                                  __half* __restrict__ bQKV, __half* __restrict__ bO)
{
    const int blk = blockIdx.x;
    const int tid = threadIdx.x;

    if (blk < ISPLIT_BLKS) {
        int i = blk * 256 + tid;
        float4 v = ((const float4*)hidden)[i];
        __half h0 = __float2half_rn(v.x), h1 = __float2half_rn(v.y);
        __half h2 = __float2half_rn(v.z), h3 = __float2half_rn(v.w);
        uint2 hv, lv;
        hv.x = pack_f16x2(__half2float(h0), __half2float(h1));
        hv.y = pack_f16x2(__half2float(h2), __half2float(h3));
        lv.x = pack_f16x2(v.x - __half2float(h0), v.y - __half2float(h1));
        lv.y = pack_f16x2(v.z - __half2float(h2), v.w - __half2float(h3));
        ((uint2*)aHi)[i] = hv;
        ((uint2*)aLo)[i] = lv;
    } else {
        __shared__ float t[32][33];
        int local = blk - ISPLIT_BLKS;
        const int ntile = local % 160;
        const int k0 = (local / 160) * 32;
        const float* W;  __half* dst;  int N;  int n0;
        if (ntile < 64)      { W = Wq; dst = bQKV;                       N = 2048; n0 = ntile * 32; }
        else if (ntile < 80) { W = Wk; dst = bQKV + (size_t)2048 * KDIM; N = 512;  n0 = (ntile - 64) * 32; }
        else if (ntile < 96) { W = Wv; dst = bQKV + (size_t)2560 * KDIM; N = 512;  n0 = (ntile - 80) * 32; }
        else                 { W = Wo; dst = bO;                         N = 2048; n0 = (ntile - 96) * 32; }

        const int tx = tid & 31, ty = tid >> 5;
        #pragma unroll
        for (int i = 0; i < 32; i += 8)
            t[ty + i][tx] = W[(size_t)(k0 + ty + i) * N + n0 + tx];
        __syncthreads();
        #pragma unroll
        for (int i = 0; i < 32; i += 8) {
            float v = t[tx][ty + i];
            dst[(size_t)(n0 + ty + i) * KDIM + k0 + tx] = __float2half_rn(v);
        }
    }
}

// ---------------- fused prep: rope(Q) | rope(K) | V-transpose ----------------
#define PREP_ROPEQ_BLKS 8192
#define PREP_ROPEK_BLKS 2048
#define PREP_VT_BLKS 1024
#define PREP_TOTAL_BLKS (PREP_ROPEQ_BLKS + PREP_ROPEK_BLKS + PREP_VT_BLKS)

__device__ __forceinline__ void rope_body(const float* __restrict__ qkv, int colOff,
                                          __half* __restrict__ hi, __half* __restrict__ lo,
                                          int heads, int idx)
{
    int dpair = idx & 31;
    int t = idx >> 5;
    int h = t % heads;  t /= heads;
    int s = t % SEQ;
    int b = t / SEQ;

    float inv = powf(10000.0f, -(float)(2 * dpair) / (float)HD);
    float ang = (float)s * inv;
    float sn, cs;
    sincosf(ang, &sn, &cs);

    size_t src = ((size_t)b * SEQ + s) * NQKV + colOff + h * HD + dpair;
    float x1 = qkv[src];
    float x2 = qkv[src + HD / 2];
    float y1 = x1 * cs - x2 * sn;
    float y2 = x2 * cs + x1 * sn;

    size_t base = (((size_t)b * SEQ + s) * heads + h) * HD + dpair;
    __half h1 = __float2half_rn(y1);
    __half h2 = __float2half_rn(y2);
    hi[base] = h1;
    hi[base + HD / 2] = h2;
    if (lo) {
        lo[base] = __float2half_rn(y1 - __half2float(h1));
        lo[base + HD / 2] = __float2half_rn(y2 - __half2float(h2));
    }
}

__global__ void prep_kernel(const float* __restrict__ qkv,
                            __half* __restrict__ qH, __half* __restrict__ qL,
                            __half* __restrict__ kH,
                            __half* __restrict__ vtH, __half* __restrict__ vtL)
{
    const int blk = blockIdx.x;
    const int tid = threadIdx.x;

    if (blk < PREP_ROPEQ_BLKS) {
        rope_body(qkv, 0, qH, qL, HQ, blk * 256 + tid);
    } else if (blk < PREP_ROPEQ_BLKS + PREP_ROPEK_BLKS) {
        rope_body(qkv, 2048, kH, (__half*)0, HKV, (blk - PREP_ROPEQ_BLKS) * 256 + tid);
    } else {
        __shared__ float t[32][33];
        int local = blk - PREP_ROPEQ_BLKS - PREP_ROPEK_BLKS;
        const int s0 = (local & 31) * 32;
        const int d0 = ((local >> 5) & 1) * 32;
        const int bh = local >> 6;
        const int b = bh >> 3;
        const int h = bh & 7;
        const int tx = tid & 31, ty = tid >> 5;
        #pragma unroll
        for (int i = 0; i < 32; i += 8)
            t[ty + i][tx] = qkv[((size_t)b * SEQ + s0 + ty + i) * NQKV + 2560 + h * HD + d0 + tx];
        __syncthreads();
        #pragma unroll
        for (int i = 0; i < 32; i += 8) {
            float x = t[tx][ty + i];
            __half hh = __float2half_rn(x);
            float r = x - __half2float(hh);
            size_t o = (((size_t)b * HKV + h) * HD + d0 + ty + i) * SEQ + s0 + tx;
            vtH[o] = hh;
            vtL[o] = __float2half_rn(r);
        }
    }
}

// ---------------- flash attention: paired q-tiles + double-buffered cp.async KV ----------------
#define FPITCH 72
#define QH_OFF 0
#define QL_OFF (128 * FPITCH)
#define KH_OFF 0
#define VH_OFF (64 * FPITCH)
#define VL_OFF (128 * FPITCH)
#define KV_STAGE_ELEMS (192 * FPITCH)              // 3 tiles x 64 rows
#define FLASH_SMEM (2 * KV_STAGE_ELEMS * 2)        // 55296 bytes
#define NQT (SEQ / 128)                            // 8 q-tiles

__device__ __forceinline__ void flash_issue_kv(
    uint32_t sb, int stage,
    const __half* __restrict__ khi,
    const __half* __restrict__ vthi, const __half* __restrict__ vtlo,
    int b, int hkv, int kt, int tid)
{
    #pragma unroll
    for (int it = 0; it < 6; it++) {
        int idx = tid + it * 256;
        int tile = idx >> 9;
        int r = (idx >> 3) & 63;
        int ch = idx & 7;
        const __half* src;
        int dstoff;
        if (tile == 0) { src = &khi[(((size_t)b * SEQ + kt * 64 + r) * HKV + hkv) * HD + ch * 8]; dstoff = KH_OFF; }
        else if (tile == 1) { src = &vthi[(((size_t)b * HKV + hkv) * HD + r) * SEQ + kt * 64 + ch * 8]; dstoff = VH_OFF; }
        else { src = &vtlo[(((size_t)b * HKV + hkv) * HD + r) * SEQ + kt * 64 + ch * 8]; dstoff = VL_OFF; }
        uint32_t dst = sb + 2u * (uint32_t)(stage * KV_STAGE_ELEMS + dstoff + r * FPITCH + ch * 8);
        asm volatile("cp.async.cg.shared.global [%0], [%1], 16;" :: "r"(dst), "l"(src));
    }
    asm volatile("cp.async.commit_group;");
}

__global__ __launch_bounds__(256, 2) void flash_mma_kernel(
    const __half* __restrict__ qhi, const __half* __restrict__ qlo,
    const __half* __restrict__ khi,
    const __half* __restrict__ vthi, const __half* __restrict__ vtlo,
    __half* __restrict__ outHi, __half* __restrict__ outLo)
{
    extern __shared__ char smem[];
    const uint32_t sb = smem_to_u32(smem);
    __half* sm = (__half*)smem;

    const int tid = threadIdx.x;
    const int wid = tid >> 5;
    const int lid = tid & 31;
    const int g = lid >> 2;
    const int t4 = lid & 3;
    const int pairIdx = blockIdx.x;      // 0..3
    const int bh = blockIdx.y;
    const int b = bh >> 5;
    const int h = bh & 31;
    const int hkv = h >> 2;

    const int arow_l = (lid & 7) + ((lid >> 3) & 1) * 8;
    const int acol_l = (lid >> 4) * 8;
    const int brow_l = (lid & 7) + (lid >> 4) * 8;
    const int bcol_l = ((lid >> 3) & 1) * 8;

    const float scale = 0.125f;

    #pragma unroll
    for (int half = 0; half < 2; half++) {
        const int qt = half ? (NQT - 1 - pairIdx) : pairIdx;

        // ---- stage Q tile (overlays KV stage memory) ----
        __syncthreads();   // all prior smem reads / cp.asyncs drained (wait_group 0 at end of prev half)
        #pragma unroll
        for (int it = 0; it < 4; it++) {
            int idx = tid + it * 256;
            int row = idx >> 3;
            int ch = idx & 7;
            size_t goff = (((size_t)b * SEQ + qt * 128 + row) * HQ + h) * HD + ch * 8;
            *(uint4*)&sm[QH_OFF + row * FPITCH + ch * 8] = *(const uint4*)&qhi[goff];
            *(uint4*)&sm[QL_OFF + row * FPITCH + ch * 8] = *(const uint4*)&qlo[goff];
        }
        __syncthreads();

        uint32_t qh[4][4], ql[4][4];
        #pragma unroll
        for (int ks = 0; ks < 4; ks++) {
            uint32_t ad = sb + 2u * (uint32_t)(QH_OFF + (wid * 16 + arow_l) * FPITCH + ks * 16 + acol_l);
            LDM4(qh[ks][0], qh[ks][1], qh[ks][2], qh[ks][3], ad);
            ad = sb + 2u * (uint32_t)(QL_OFF + (wid * 16 + arow_l) * FPITCH + ks * 16 + acol_l);
            LDM4(ql[ks][0], ql[ks][1], ql[ks][2], ql[ks][3], ad);
        }
        __syncthreads();   // Q fragments in regs before KV overwrites the region

        float m0 = -1e30f, m1 = -1e30f, l0 = 0.f, l1 = 0.f;
        float oacc[8][4];
        #pragma unroll
        for (int nt = 0; nt < 8; nt++)
            #pragma unroll
            for (int r = 0; r < 4; r++) oacc[nt][r] = 0.f;

        const int row0 = qt * 128 + wid * 16;
        const int r_g = row0 + g;
        const int r_g8 = r_g + 8;
        const int nkt = 2 * qt + 2;

        // prime the KV pipeline
        flash_issue_kv(sb, 0, khi, vthi, vtlo, b, hkv, 0, tid);

        for (int kt = 0; kt < nkt; kt++) {
            const int stg = kt & 1;
            if (kt + 1 < nkt) {
                flash_issue_kv(sb, 1 - stg, khi, vthi, vtlo, b, hkv, kt + 1, tid);
                asm volatile("cp.async.wait_group 1;" ::: "memory");
            } else {
                asm volatile("cp.async.wait_group 0;" ::: "memory");
            }
            __syncthreads();

            const uint32_t kvb = sb + 2u * (uint32_t)(stg * KV_STAGE_ELEMS);

            float sacc[8][4];
            #pragma unroll
            for (int nt = 0; nt < 8; nt++)
                #pragma unroll
                for (int r = 0; r < 4; r++) sacc[nt][r] = 0.f;

            #pragma unroll
            for (int ks = 0; ks < 4; ks++) {
                uint32_t kf[4][4];
                #pragma unroll
                for (int ntp = 0; ntp < 4; ntp++) {
                    uint32_t bd = kvb + 2u * (uint32_t)(KH_OFF + (ntp * 16 + brow_l) * FPITCH + ks * 16 + bcol_l);
                    LDM4(kf[ntp][0], kf[ntp][1], kf[ntp][2], kf[ntp][3], bd);
                }
                #pragma unroll
                for (int ntp = 0; ntp < 4; ntp++) {
                    mma16816(sacc[2 * ntp],     qh[ks], kf[ntp][0], kf[ntp][1]);
                    mma16816(sacc[2 * ntp + 1], qh[ks], kf[ntp][2], kf[ntp][3]);
                }
                #pragma unroll
                for (int ntp = 0; ntp < 4; ntp++) {
                    mma16816(sacc[2 * ntp],     ql[ks], kf[ntp][0], kf[ntp][1]);
                    mma16816(sacc[2 * ntp + 1], ql[ks], kf[ntp][2], kf[ntp][3]);
                }
            }

            const bool maybe_mask = (kt * 64 + 63 > row0);
            float mx0 = -1e30f, mx1 = -1e30f;
            #pragma unroll
            for (int nt = 0; nt < 8; nt++) {
                #pragma unroll
                for (int r = 0; r < 4; r++) sacc[nt][r] *= scale;
                if (maybe_mask) {
                    int colb = kt * 64 + nt * 8 + 2 * t4;
                    if (colb > r_g)      sacc[nt][0] = NEG_BIG;
                    if (colb + 1 > r_g)  sacc[nt][1] = NEG_BIG;
                    if (colb > r_g8)     sacc[nt][2] = NEG_BIG;
                    if (colb + 1 > r_g8) sacc[nt][3] = NEG_BIG;
                }
                mx0 = fmaxf(mx0, fmaxf(sacc[nt][0], sacc[nt][1]));
                mx1 = fmaxf(mx1, fmaxf(sacc[nt][2], sacc[nt][3]));
            }
            mx0 = fmaxf(mx0, __shfl_xor_sync(0xffffffffu, mx0, 1));
            mx0 = fmaxf(mx0, __shfl_xor_sync(0xffffffffu, mx0, 2));
            mx1 = fmaxf(mx1, __shfl_xor_sync(0xffffffffu, mx1, 1));
            mx1 = fmaxf(mx1, __shfl_xor_sync(0xffffffffu, mx1, 2));

            float mn0 = fmaxf(m0, mx0), mn1 = fmaxf(m1, mx1);
            float corr0 = __expf(m0 - mn0), corr1 = __expf(m1 - mn1);

            uint32_t ph[8][2];
            float rs0 = 0.f, rs1 = 0.f;
            #pragma unroll
            for (int nt = 0; nt < 8; nt++) {
                float p00 = __expf(sacc[nt][0] - mn0);
                float p01 = __expf(sacc[nt][1] - mn0);
                float p10 = __expf(sacc[nt][2] - mn1);
                float p11 = __expf(sacc[nt][3] - mn1);
                rs0 += p00 + p01;
                rs1 += p10 + p11;
                ph[nt][0] = pack_f16x2(p00, p01);
                ph[nt][1] = pack_f16x2(p10, p11);
            }
            rs0 += __shfl_xor_sync(0xffffffffu, rs0, 1);
            rs0 += __shfl_xor_sync(0xffffffffu, rs0, 2);
            rs1 += __shfl_xor_sync(0xffffffffu, rs1, 1);
            rs1 += __shfl_xor_sync(0xffffffffu, rs1, 2);

            l0 = l0 * corr0 + rs0;
            l1 = l1 * corr1 + rs1;
            m0 = mn0; m1 = mn1;
            #pragma unroll
            for (int nt = 0; nt < 8; nt++) {
                oacc[nt][0] *= corr0; oacc[nt][1] *= corr0;
                oacc[nt][2] *= corr1; oacc[nt][3] *= corr1;
            }

            #pragma unroll
            for (int ks = 0; ks < 4; ks++) {
                uint32_t pah[4] = { ph[2 * ks][0], ph[2 * ks][1], ph[2 * ks + 1][0], ph[2 * ks + 1][1] };
                uint32_t vfh[4][4], vfl[4][4];
                #pragma unroll
                for (int ntp = 0; ntp < 4; ntp++) {
                    uint32_t bd = kvb + 2u * (uint32_t)(VH_OFF + (ntp * 16 + brow_l) * FPITCH + ks * 16 + bcol_l);
                    LDM4(vfh[ntp][0], vfh[ntp][1], vfh[ntp][2], vfh[ntp][3], bd);
                    bd = kvb + 2u * (uint32_t)(VL_OFF + (ntp * 16 + brow_l) * FPITCH + ks * 16 + bcol_l);
                    LDM4(vfl[ntp][0], vfl[ntp][1], vfl[ntp][2], vfl[ntp][3], bd);
                }
                #pragma unroll
                for (int ntp = 0; ntp < 4; ntp++) {
                    mma16816(oacc[2 * ntp],     pah, vfh[ntp][0], vfh[ntp][1]);
                    mma16816(oacc[2 * ntp + 1], pah, vfh[ntp][2], vfh[ntp][3]);
                }
                #pragma unroll
                for (int ntp = 0; ntp < 4; ntp++) {
                    mma16816(oacc[2 * ntp],     pah, vfl[ntp][0], vfl[ntp][1]);
                    mma16816(oacc[2 * ntp + 1], pah, vfl[ntp][2], vfl[ntp][3]);
                }
            }
            __syncthreads();   // protects the stage being overwritten by the next prefetch
        }

        // ---- epilogue for this q-tile ----
        float inv0 = 1.0f / l0, inv1 = 1.0f / l1;
        uint32_t* oHi = (uint32_t*)outHi;
        uint32_t* oLo = (uint32_t*)outLo;
        #pragma unroll
        for (int nt = 0; nt < 8; nt++) {
            float o00 = oacc[nt][0] * inv0, o01 = oacc[nt][1] * inv0;
            float o10 = oacc[nt][2] * inv1, o11 = oacc[nt][3] * inv1;
            float h00 = __half2float(__float2half_rn(o00));
            float h01 = __half2float(__float2half_rn(o01));
            float h10 = __half2float(__float2half_rn(o10));
            float h11 = __half2float(__float2half_rn(o11));
            size_t row = (size_t)b * SEQ + qt * 128 + wid * 16 + g;
            int col = h * 64 + nt * 8 + 2 * t4;
            oHi[(row * 2048 + col) >> 1] = pack_f16x2(h00, h01);
            oLo[(row * 2048 + col) >> 1] = pack_f16x2(o00 - h00, o01 - h01);
            oHi[((row + 8) * 2048 + col) >> 1] = pack_f16x2(h10, h11);
            oLo[((row + 8) * 2048 + col) >> 1] = pack_f16x2(o10 - h10, o11 - h11);
        }
    }
}

// ---------------- launcher ----------------
extern "C" void kernel_launch(void* const* d_in, const int* in_sizes, int n_in,
                              void* d_out, int out_size)
{
    const float* hidden = (const float*)d_in[0];
    const float* Wq = (const float*)d_in[2];
    const float* Wk = (const float*)d_in[3];
    const float* Wv = (const float*)d_in[4];
    const float* Wo = (const float*)d_in[5];
    float* out = (float*)d_out;

    float* qkv_ptr;
    cudaGetSymbolAddress((void**)&qkv_ptr, g_qkv);

    __half *aHi, *aLo, *bQKV, *bO;
    __half *qH, *qL, *kH, *vtH, *vtL;
    cudaGetSymbolAddress((void**)&aHi, gA_hi);
    cudaGetSymbolAddress((void**)&aLo, gA_lo);
    cudaGetSymbolAddress((void**)&bQKV, gBqkv);
    cudaGetSymbolAddress((void**)&bO, gBo);
    cudaGetSymbolAddress((void**)&qH, gQhi);
    cudaGetSymbolAddress((void**)&qL, gQlo);
    cudaGetSymbolAddress((void**)&kH, gKhi);
    cudaGetSymbolAddress((void**)&vtH, gVThi);
    cudaGetSymbolAddress((void**)&vtL, gVTlo);

    cudaFuncSetAttribute(gemm_fp16x2_kernel, cudaFuncAttributeMaxDynamicSharedMemorySize, GEMM_SMEM);
    cudaFuncSetAttribute(flash_mma_kernel, cudaFuncAttributeMaxDynamicSharedMemorySize, FLASH_SMEM);

    // 1) fused input prep
    input_prep_kernel<<<IN_TOTAL_BLKS, 256>>>(hidden, Wq, Wk, Wv, Wo, aHi, aLo, bQKV, bO);

    // 2) fused QKV projection
    gemm_fp16x2_kernel<<<dim3(NQKV / 128, MROWS / 64), 128, GEMM_SMEM>>>(aHi, aLo, bQKV, qkv_ptr, NQKV);

    // 3) fused prep (rope Q, rope K, V transpose)
    prep_kernel<<<PREP_TOTAL_BLKS, 256>>>(qkv_ptr, qH, qL, kH, vtH, vtL);

    // 4) attention (paired q-tiles, double-buffered KV)
    {
        dim3 g(NQT / 2, BATCH * HQ);
        flash_mma_kernel<<<g, 256, FLASH_SMEM>>>(qH, qL, kH, vtH, vtL, aHi, aLo);
    }

    // 5) output projection
    gemm_fp16x2_kernel<<<dim3(2048 / 128, MROWS / 64), 128, GEMM_SMEM>>>(aHi, aLo, bO, out, 2048);
}

// round 13
// speedup vs baseline: 1.0032x; 1.0032x over previous
#include <cuda_runtime.h>
#include <cuda_fp16.h>
#include <math.h>
#include <stdint.h>

// ---------------- problem constants ----------------
#define BATCH 2
#define SEQ 1024
#define HIDDEN 2048
#define HQ 32
#define HKV 8
#define HD 64
#define MROWS (BATCH * SEQ)     // 2048
#define KDIM HIDDEN             // 2048
#define NQKV 3072
#define NEG_BIG (-1e9f)

// ---------------- scratch ----------------
__device__ float g_qkv[MROWS * NQKV];

__device__ __half gA_hi[MROWS * KDIM];
__device__ __half gA_lo[MROWS * KDIM];
__device__ __half gBqkv[NQKV * KDIM];
__device__ __half gBo[2048 * KDIM];

__device__ __half gQhi[MROWS * HQ * HD];
__device__ __half gQlo[MROWS * HQ * HD];
__device__ __half gKhi[MROWS * HKV * HD];
__device__ __half gVThi[BATCH * HKV * HD * SEQ];
__device__ __half gVTlo[BATCH * HKV * HD * SEQ];

// ---------------- helpers ----------------
__device__ __forceinline__ uint32_t smem_to_u32(const void* p) {
    uint32_t a;
    asm("{ .reg .u64 t; cvta.to.shared.u64 t, %1; cvt.u32.u64 %0, t; }" : "=r"(a) : "l"(p));
    return a;
}
#define LDM4(r0, r1, r2, r3, addr) \
    asm volatile("ldmatrix.sync.aligned.m8n8.x4.shared.b16 {%0,%1,%2,%3}, [%4];" \
        : "=r"(r0), "=r"(r1), "=r"(r2), "=r"(r3) : "r"(addr))

__device__ __forceinline__ void mma16816(float* d, const uint32_t* a, uint32_t b0, uint32_t b1) {
    asm volatile("mma.sync.aligned.m16n8k16.row.col.f32.f16.f16.f32 "
        "{%0,%1,%2,%3}, {%4,%5,%6,%7}, {%8,%9}, {%0,%1,%2,%3};"
        : "+f"(d[0]), "+f"(d[1]), "+f"(d[2]), "+f"(d[3])
        : "r"(a[0]), "r"(a[1]), "r"(a[2]), "r"(a[3]), "r"(b0), "r"(b1));
}
__device__ __forceinline__ uint32_t pack_f16x2(float lo, float hi) {
    uint32_t d;
    asm("cvt.rn.f16x2.f32 %0, %1, %2;" : "=r"(d) : "f"(hi), "f"(lo));
    return d;
}

// ---------------- fp16x2 GEMM (R9 config): 64x128 tile, BK=32, 3 stages, occ 3 ----------------
#define BK 32
#define PITCH 40
#define A_ELEMS (64 * PITCH)
#define B_ELEMS (128 * PITCH)
#define STAGE_ELEMS (2 * A_ELEMS + B_ELEMS)
#define NSTAGE 3
#define GEMM_SMEM (NSTAGE * STAGE_ELEMS * 2)        // 61440 bytes
#define NCHUNK (KDIM / BK)

__device__ __forceinline__ void issue_stage(
    uint32_t sb, int stage,
    const __half* __restrict__ Ahi, const __half* __restrict__ Alo,
    const __half* __restrict__ B,
    int m0, int n0, int k0, int tid)
{
    #pragma unroll
    for (int t = 0; t < 8; t++) {
        int idx = tid + t * 128;
        int ch = idx & 3;
        const __half* src;
        uint32_t dstoff;
        if (idx < 512) {
            int tl = idx >> 8;
            int row = (idx >> 2) & 63;
            src = (tl ? Alo : Ahi) + (size_t)(m0 + row) * KDIM + k0 + ch * 8;
            dstoff = (uint32_t)(tl * A_ELEMS + row * PITCH + ch * 8);
        } else {
            int row = (idx >> 2) & 127;
            src = B + (size_t)(n0 + row) * KDIM + k0 + ch * 8;
            dstoff = (uint32_t)(2 * A_ELEMS + row * PITCH + ch * 8);
        }
        uint32_t dst = sb + 2u * ((uint32_t)stage * STAGE_ELEMS + dstoff);
        asm volatile("cp.async.cg.shared.global [%0], [%1], 16;" :: "r"(dst), "l"(src));
    }
    asm volatile("cp.async.commit_group;");
}

__global__ __launch_bounds__(128, 3) void gemm_fp16x2_kernel(
    const __half* __restrict__ Ahi, const __half* __restrict__ Alo,
    const __half* __restrict__ B,
    float* __restrict__ C, int N)
{
    extern __shared__ char smem[];
    const uint32_t sb = smem_to_u32(smem);
    const int tid = threadIdx.x;
    const int wid = tid >> 5;
    const int lid = tid & 31;
    const int g = lid >> 2;
    const int t4 = lid & 3;
    const int n0 = blockIdx.x * 128;
    const int m0 = blockIdx.y * 64;

    const int arow_l = (lid & 7) + ((lid >> 3) & 1) * 8;
    const int acol_l = (lid >> 4) * 8;
    const int brow_l = (lid & 7) + (lid >> 4) * 8;
    const int bcol_l = ((lid >> 3) & 1) * 8;

    float acc[4][4][4];
    #pragma unroll
    for (int i = 0; i < 4; i++)
        #pragma unroll
        for (int j = 0; j < 4; j++)
            #pragma unroll
            for (int r = 0; r < 4; r++) acc[i][j][r] = 0.f;

    issue_stage(sb, 0, Ahi, Alo, B, m0, n0, 0, tid);
    issue_stage(sb, 1, Ahi, Alo, B, m0, n0, BK, tid);

    int p = 0;
    for (int i = 0; i < NCHUNK; i++) {
        if (i < NCHUNK - 1) {
            asm volatile("cp.async.wait_group 1;" ::: "memory");
        } else {
            asm volatile("cp.async.wait_group 0;" ::: "memory");
        }
        __syncthreads();

        if (i + 2 < NCHUNK) {
            int st = p + 2; if (st >= NSTAGE) st -= NSTAGE;
            issue_stage(sb, st, Ahi, Alo, B, m0, n0, (i + 2) * BK, tid);
        }

        const uint32_t base = sb + 2u * (uint32_t)(p * STAGE_ELEMS);
        #pragma unroll
        for (int ks = 0; ks < 2; ks++) {
            const int kb = ks * 16;
            uint32_t ah[4][4], al[4][4], bb[4][2];
            #pragma unroll
            for (int mt = 0; mt < 4; mt++) {
                uint32_t ad = base + 2u * (uint32_t)((mt * 16 + arow_l) * PITCH + kb + acol_l);
                LDM4(ah[mt][0], ah[mt][1], ah[mt][2], ah[mt][3], ad);
                LDM4(al[mt][0], al[mt][1], al[mt][2], al[mt][3], ad + 2u * A_ELEMS);
            }
            #pragma unroll
            for (int ntp = 0; ntp < 2; ntp++) {
                uint32_t bd = base + 2u * (uint32_t)(2 * A_ELEMS + (wid * 32 + ntp * 16 + brow_l) * PITCH + kb + bcol_l);
                uint32_t r0, r1, r2, r3;
                LDM4(r0, r1, r2, r3, bd);
                bb[2 * ntp][0] = r0; bb[2 * ntp][1] = r1;
                bb[2 * ntp + 1][0] = r2; bb[2 * ntp + 1][1] = r3;
            }
            #pragma unroll
            for (int mt = 0; mt < 4; mt++)
                #pragma unroll
                for (int nt = 0; nt < 4; nt++)
                    mma16816(acc[mt][nt], ah[mt], bb[nt][0], bb[nt][1]);
            #pragma unroll
            for (int mt = 0; mt < 4; mt++)
                #pragma unroll
                for (int nt = 0; nt < 4; nt++)
                    mma16816(acc[mt][nt], al[mt], bb[nt][0], bb[nt][1]);
        }
        if (++p == NSTAGE) p = 0;
    }

    #pragma unroll
    for (int mt = 0; mt < 4; mt++) {
        int row = m0 + mt * 16 + g;
        #pragma unroll
        for (int nt = 0; nt < 4; nt++) {
            int col = n0 + wid * 32 + nt * 8 + 2 * t4;
            *(float2*)&C[(size_t)row * N + col] = make_float2(acc[mt][nt][0], acc[mt][nt][1]);
            *(float2*)&C[(size_t)(row + 8) * N + col] = make_float2(acc[mt][nt][2], acc[mt][nt][3]);
        }
    }
}

// ---------------- fused input prep ----------------
#define ISPLIT_BLKS 4096
#define WT_BLKS (160 * 64)
#define IN_TOTAL_BLKS (ISPLIT_BLKS + WT_BLKS)

__global__ void input_prep_kernel(const float* __restrict__ hidden,
                                  const float* __restrict__ Wq, const float* __restrict__ Wk,
                                  const float* __restrict__ Wv, const float* __restrict__ Wo,
                                  __half* __restrict__ aHi, __half* __restrict__ aLo,
                                  __half* __restrict__ bQKV, __half* __restrict__ bO)
{
    const int blk = blockIdx.x;
    const int tid = threadIdx.x;

    if (blk < ISPLIT_BLKS) {
        int i = blk * 256 + tid;
        float4 v = ((const float4*)hidden)[i];
        __half h0 = __float2half_rn(v.x), h1 = __float2half_rn(v.y);
        __half h2 = __float2half_rn(v.z), h3 = __float2half_rn(v.w);
        uint2 hv, lv;
        hv.x = pack_f16x2(__half2float(h0), __half2float(h1));
        hv.y = pack_f16x2(__half2float(h2), __half2float(h3));
        lv.x = pack_f16x2(v.x - __half2float(h0), v.y - __half2float(h1));
        lv.y = pack_f16x2(v.z - __half2float(h2), v.w - __half2float(h3));
        ((uint2*)aHi)[i] = hv;
        ((uint2*)aLo)[i] = lv;
    } else {
        __shared__ float t[32][33];
        int local = blk - ISPLIT_BLKS;
        const int ntile = local % 160;
        const int k0 = (local / 160) * 32;
        const float* W;  __half* dst;  int N;  int n0;
        if (ntile < 64)      { W = Wq; dst = bQKV;                       N = 2048; n0 = ntile * 32; }
        else if (ntile < 80) { W = Wk; dst = bQKV + (size_t)2048 * KDIM; N = 512;  n0 = (ntile - 64) * 32; }
        else if (ntile < 96) { W = Wv; dst = bQKV + (size_t)2560 * KDIM; N = 512;  n0 = (ntile - 80) * 32; }
        else                 { W = Wo; dst = bO;                         N = 2048; n0 = (ntile - 96) * 32; }

        const int tx = tid & 31, ty = tid >> 5;
        #pragma unroll
        for (int i = 0; i < 32; i += 8)
            t[ty + i][tx] = W[(size_t)(k0 + ty + i) * N + n0 + tx];
        __syncthreads();
        #pragma unroll
        for (int i = 0; i < 32; i += 8) {
            float v = t[tx][ty + i];
            dst[(size_t)(n0 + ty + i) * KDIM + k0 + tx] = __float2half_rn(v);
        }
    }
}

// ---------------- fused prep: rope(Q) | rope(K) | V-transpose ----------------
#define PREP_ROPEQ_BLKS 8192
#define PREP_ROPEK_BLKS 2048
#define PREP_VT_BLKS 1024
#define PREP_TOTAL_BLKS (PREP_ROPEQ_BLKS + PREP_ROPEK_BLKS + PREP_VT_BLKS)

__device__ __forceinline__ void rope_body(const float* __restrict__ qkv, int colOff,
                                          __half* __restrict__ hi, __half* __restrict__ lo,
                                          int heads, int idx)
{
    int dpair = idx & 31;
    int t = idx >> 5;
    int h = t % heads;  t /= heads;
    int s = t % SEQ;
    int b = t / SEQ;

    float inv = powf(10000.0f, -(float)(2 * dpair) / (float)HD);
    float ang = (float)s * inv;
    float sn, cs;
    sincosf(ang, &sn, &cs);

    size_t src = ((size_t)b * SEQ + s) * NQKV + colOff + h * HD + dpair;
    float x1 = qkv[src];
    float x2 = qkv[src + HD / 2];
    float y1 = x1 * cs - x2 * sn;
    float y2 = x2 * cs + x1 * sn;

    size_t base = (((size_t)b * SEQ + s) * heads + h) * HD + dpair;
    __half h1 = __float2half_rn(y1);
    __half h2 = __float2half_rn(y2);
    hi[base] = h1;
    hi[base + HD / 2] = h2;
    if (lo) {
        lo[base] = __float2half_rn(y1 - __half2float(h1));
        lo[base + HD / 2] = __float2half_rn(y2 - __half2float(h2));
    }
}

__global__ void prep_kernel(const float* __restrict__ qkv,
                            __half* __restrict__ qH, __half* __restrict__ qL,
                            __half* __restrict__ kH,
                            __half* __restrict__ vtH, __half* __restrict__ vtL)
{
    const int blk = blockIdx.x;
    const int tid = threadIdx.x;

    if (blk < PREP_ROPEQ_BLKS) {
        rope_body(qkv, 0, qH, qL, HQ, blk * 256 + tid);
    } else if (blk < PREP_ROPEQ_BLKS + PREP_ROPEK_BLKS) {
        rope_body(qkv, 2048, kH, (__half*)0, HKV, (blk - PREP_ROPEQ_BLKS) * 256 + tid);
    } else {
        __shared__ float t[32][33];
        int local = blk - PREP_ROPEQ_BLKS - PREP_ROPEK_BLKS;
        const int s0 = (local & 31) * 32;
        const int d0 = ((local >> 5) & 1) * 32;
        const int bh = local >> 6;
        const int b = bh >> 3;
        const int h = bh & 7;
        const int tx = tid & 31, ty = tid >> 5;
        #pragma unroll
        for (int i = 0; i < 32; i += 8)
            t[ty + i][tx] = qkv[((size_t)b * SEQ + s0 + ty + i) * NQKV + 2560 + h * HD + d0 + tx];
        __syncthreads();
        #pragma unroll
        for (int i = 0; i < 32; i += 8) {
            float x = t[tx][ty + i];
            __half hh = __float2half_rn(x);
            float r = x - __half2float(hh);
            size_t o = (((size_t)b * HKV + h) * HD + d0 + ty + i) * SEQ + s0 + tx;
            vtH[o] = hh;
            vtL[o] = __float2half_rn(r);
        }
    }
}

// ---------------- flash: 128 threads, 64-row q-tiles, occ 4, paired (p, 15-p) ----------------
#define FPITCH 72
#define QH_OFF 0
#define QL_OFF (64 * FPITCH)
#define KH_OFF 0
#define VH_OFF (64 * FPITCH)
#define VL_OFF (128 * FPITCH)
#define KV_STAGE_ELEMS (192 * FPITCH)              // 3 tiles x 64 rows
#define FLASH_SMEM (2 * KV_STAGE_ELEMS * 2)        // 55296 bytes
#define NQT64 (SEQ / 64)                           // 16 q-tiles of 64 rows

__device__ __forceinline__ void flash_issue_kv(
    uint32_t sb, int stage,
    const __half* __restrict__ khi,
    const __half* __restrict__ vthi, const __half* __restrict__ vtlo,
    int b, int hkv, int kt, int tid)
{
    #pragma unroll
    for (int it = 0; it < 12; it++) {
        int idx = tid + it * 128;           // 0..1535
        int tile = idx >> 9;
        int r = (idx >> 3) & 63;
        int ch = idx & 7;
        const __half* src;
        int dstoff;
        if (tile == 0) { src = &khi[(((size_t)b * SEQ + kt * 64 + r) * HKV + hkv) * HD + ch * 8]; dstoff = KH_OFF; }
        else if (tile == 1) { src = &vthi[(((size_t)b * HKV + hkv) * HD + r) * SEQ + kt * 64 + ch * 8]; dstoff = VH_OFF; }
        else { src = &vtlo[(((size_t)b * HKV + hkv) * HD + r) * SEQ + kt * 64 + ch * 8]; dstoff = VL_OFF; }
        uint32_t dst = sb + 2u * (uint32_t)(stage * KV_STAGE_ELEMS + dstoff + r * FPITCH + ch * 8);
        asm volatile("cp.async.cg.shared.global [%0], [%1], 16;" :: "r"(dst), "l"(src));
    }
    asm volatile("cp.async.commit_group;");
}

__global__ __launch_bounds__(128, 4) void flash_mma_kernel(
    const __half* __restrict__ qhi, const __half* __restrict__ qlo,
    const __half* __restrict__ khi,
    const __half* __restrict__ vthi, const __half* __restrict__ vtlo,
    __half* __restrict__ outHi, __half* __restrict__ outLo)
{
    extern __shared__ char smem[];
    const uint32_t sb = smem_to_u32(smem);
    __half* sm = (__half*)smem;

    const int tid = threadIdx.x;
    const int wid = tid >> 5;            // 0..3
    const int lid = tid & 31;
    const int g = lid >> 2;
    const int t4 = lid & 3;
    const int pairIdx = blockIdx.x;      // 0..7
    const int bh = blockIdx.y;
    const int b = bh >> 5;
    const int h = bh & 31;
    const int hkv = h >> 2;

    const int arow_l = (lid & 7) + ((lid >> 3) & 1) * 8;
    const int acol_l = (lid >> 4) * 8;
    const int brow_l = (lid & 7) + (lid >> 4) * 8;
    const int bcol_l = ((lid >> 3) & 1) * 8;

    const float scale = 0.125f;

    #pragma unroll
    for (int half = 0; half < 2; half++) {
        const int qt = half ? (NQT64 - 1 - pairIdx) : pairIdx;

        // ---- stage Q tile (64 x 64 hi + lo, overlays KV stage memory) ----
        __syncthreads();
        #pragma unroll
        for (int it = 0; it < 8; it++) {
            int idx = tid + it * 128;        // 0..1023
            int tl = idx >> 9;               // 0=hi, 1=lo
            int row = (idx >> 3) & 63;
            int ch = idx & 7;
            size_t goff = (((size_t)b * SEQ + qt * 64 + row) * HQ + h) * HD + ch * 8;
            const __half* src = tl ? &qlo[goff] : &qhi[goff];
            int dstoff = tl ? QL_OFF : QH_OFF;
            *(uint4*)&sm[dstoff + row * FPITCH + ch * 8] = *(const uint4*)src;
        }
        __syncthreads();

        uint32_t qh[4][4], ql[4][4];
        #pragma unroll
        for (int ks = 0; ks < 4; ks++) {
            uint32_t ad = sb + 2u * (uint32_t)(QH_OFF + (wid * 16 + arow_l) * FPITCH + ks * 16 + acol_l);
            LDM4(qh[ks][0], qh[ks][1], qh[ks][2], qh[ks][3], ad);
            ad = sb + 2u * (uint32_t)(QL_OFF + (wid * 16 + arow_l) * FPITCH + ks * 16 + acol_l);
            LDM4(ql[ks][0], ql[ks][1], ql[ks][2], ql[ks][3], ad);
        }
        __syncthreads();

        float m0 = -1e30f, m1 = -1e30f, l0 = 0.f, l1 = 0.f;
        float oacc[8][4];
        #pragma unroll
        for (int nt = 0; nt < 8; nt++)
            #pragma unroll
            for (int r = 0; r < 4; r++) oacc[nt][r] = 0.f;

        const int row0 = qt * 64 + wid * 16;
        const int r_g = row0 + g;
        const int r_g8 = r_g + 8;
        const int nkt = qt + 1;

        flash_issue_kv(sb, 0, khi, vthi, vtlo, b, hkv, 0, tid);

        for (int kt = 0; kt < nkt; kt++) {
            const int stg = kt & 1;
            if (kt + 1 < nkt) {
                flash_issue_kv(sb, 1 - stg, khi, vthi, vtlo, b, hkv, kt + 1, tid);
                asm volatile("cp.async.wait_group 1;" ::: "memory");
            } else {
                asm volatile("cp.async.wait_group 0;" ::: "memory");
            }
            __syncthreads();

            const uint32_t kvb = sb + 2u * (uint32_t)(stg * KV_STAGE_ELEMS);

            float sacc[8][4];
            #pragma unroll
            for (int nt = 0; nt < 8; nt++)
                #pragma unroll
                for (int r = 0; r < 4; r++) sacc[nt][r] = 0.f;

            #pragma unroll
            for (int ks = 0; ks < 4; ks++) {
                uint32_t kf[4][4];
                #pragma unroll
                for (int ntp = 0; ntp < 4; ntp++) {
                    uint32_t bd = kvb + 2u * (uint32_t)(KH_OFF + (ntp * 16 + brow_l) * FPITCH + ks * 16 + bcol_l);
                    LDM4(kf[ntp][0], kf[ntp][1], kf[ntp][2], kf[ntp][3], bd);
                }
                #pragma unroll
                for (int ntp = 0; ntp < 4; ntp++) {
                    mma16816(sacc[2 * ntp],     qh[ks], kf[ntp][0], kf[ntp][1]);
                    mma16816(sacc[2 * ntp + 1], qh[ks], kf[ntp][2], kf[ntp][3]);
                }
                #pragma unroll
                for (int ntp = 0; ntp < 4; ntp++) {
                    mma16816(sacc[2 * ntp],     ql[ks], kf[ntp][0], kf[ntp][1]);
                    mma16816(sacc[2 * ntp + 1], ql[ks], kf[ntp][2], kf[ntp][3]);
                }
            }

            const bool maybe_mask = (kt * 64 + 63 > row0);
            float mx0 = -1e30f, mx1 = -1e30f;
            #pragma unroll
            for (int nt = 0; nt < 8; nt++) {
                #pragma unroll
                for (int r = 0; r < 4; r++) sacc[nt][r] *= scale;
                if (maybe_mask) {
                    int colb = kt * 64 + nt * 8 + 2 * t4;
                    if (colb > r_g)      sacc[nt][0] = NEG_BIG;
                    if (colb + 1 > r_g)  sacc[nt][1] = NEG_BIG;
                    if (colb > r_g8)     sacc[nt][2] = NEG_BIG;
                    if (colb + 1 > r_g8) sacc[nt][3] = NEG_BIG;
                }
                mx0 = fmaxf(mx0, fmaxf(sacc[nt][0], sacc[nt][1]));
                mx1 = fmaxf(mx1, fmaxf(sacc[nt][2], sacc[nt][3]));
            }
            mx0 = fmaxf(mx0, __shfl_xor_sync(0xffffffffu, mx0, 1));
            mx0 = fmaxf(mx0, __shfl_xor_sync(0xffffffffu, mx0, 2));
            mx1 = fmaxf(mx1, __shfl_xor_sync(0xffffffffu, mx1, 1));
            mx1 = fmaxf(mx1, __shfl_xor_sync(0xffffffffu, mx1, 2));

            float mn0 = fmaxf(m0, mx0), mn1 = fmaxf(m1, mx1);
            float corr0 = __expf(m0 - mn0), corr1 = __expf(m1 - mn1);

            uint32_t ph[8][2];
            float rs0 = 0.f, rs1 = 0.f;
            #pragma unroll
            for (int nt = 0; nt < 8; nt++) {
                float p00 = __expf(sacc[nt][0] - mn0);
                float p01 = __expf(sacc[nt][1] - mn0);
                float p10 = __expf(sacc[nt][2] - mn1);
                float p11 = __expf(sacc[nt][3] - mn1);
                rs0 += p00 + p01;
                rs1 += p10 + p11;
                ph[nt][0] = pack_f16x2(p00, p01);
                ph[nt][1] = pack_f16x2(p10, p11);
            }
            rs0 += __shfl_xor_sync(0xffffffffu, rs0, 1);
            rs0 += __shfl_xor_sync(0xffffffffu, rs0, 2);
            rs1 += __shfl_xor_sync(0xffffffffu, rs1, 1);
            rs1 += __shfl_xor_sync(0xffffffffu, rs1, 2);

            l0 = l0 * corr0 + rs0;
            l1 = l1 * corr1 + rs1;
            m0 = mn0; m1 = mn1;
            #pragma unroll
            for (int nt = 0; nt < 8; nt++) {
                oacc[nt][0] *= corr0; oacc[nt][1] *= corr0;
                oacc[nt][2] *= corr1; oacc[nt][3] *= corr1;
            }

            #pragma unroll
            for (int ks = 0; ks < 4; ks++) {
                uint32_t pah[4] = { ph[2 * ks][0], ph[2 * ks][1], ph[2 * ks + 1][0], ph[2 * ks + 1][1] };
                uint32_t vfh[4][4], vfl[4][4];
                #pragma unroll
                for (int ntp = 0; ntp < 4; ntp++) {
                    uint32_t bd = kvb + 2u * (uint32_t)(VH_OFF + (ntp * 16 + brow_l) * FPITCH + ks * 16 + bcol_l);
                    LDM4(vfh[ntp][0], vfh[ntp][1], vfh[ntp][2], vfh[ntp][3], bd);
                    bd = kvb + 2u * (uint32_t)(VL_OFF + (ntp * 16 + brow_l) * FPITCH + ks * 16 + bcol_l);
                    LDM4(vfl[ntp][0], vfl[ntp][1], vfl[ntp][2], vfl[ntp][3], bd);
                }
                #pragma unroll
                for (int ntp = 0; ntp < 4; ntp++) {
                    mma16816(oacc[2 * ntp],     pah, vfh[ntp][0], vfh[ntp][1]);
                    mma16816(oacc[2 * ntp + 1], pah, vfh[ntp][2], vfh[ntp][3]);
                }
                #pragma unroll
                for (int ntp = 0; ntp < 4; ntp++) {
                    mma16816(oacc[2 * ntp],     pah, vfl[ntp][0], vfl[ntp][1]);
                    mma16816(oacc[2 * ntp + 1], pah, vfl[ntp][2], vfl[ntp][3]);
                }
            }
            __syncthreads();
        }

        // ---- epilogue for this q-tile ----
        float inv0 = 1.0f / l0, inv1 = 1.0f / l1;
        uint32_t* oHi = (uint32_t*)outHi;
        uint32_t* oLo = (uint32_t*)outLo;
        #pragma unroll
        for (int nt = 0; nt < 8; nt++) {
            float o00 = oacc[nt][0] * inv0, o01 = oacc[nt][1] * inv0;
            float o10 = oacc[nt][2] * inv1, o11 = oacc[nt][3] * inv1;
            float h00 = __half2float(__float2half_rn(o00));
            float h01 = __half2float(__float2half_rn(o01));
            float h10 = __half2float(__float2half_rn(o10));
            float h11 = __half2float(__float2half_rn(o11));
            size_t row = (size_t)b * SEQ + qt * 64 + wid * 16 + g;
            int col = h * 64 + nt * 8 + 2 * t4;
            oHi[(row * 2048 + col) >> 1] = pack_f16x2(h00, h01);
            oLo[(row * 2048 + col) >> 1] = pack_f16x2(o00 - h00, o01 - h01);
            oHi[((row + 8) * 2048 + col) >> 1] = pack_f16x2(h10, h11);
            oLo[((row + 8) * 2048 + col) >> 1] = pack_f16x2(o10 - h10, o11 - h11);
        }
    }
}

// ---------------- launcher ----------------
extern "C" void kernel_launch(void* const* d_in, const int* in_sizes, int n_in,
                              void* d_out, int out_size)
{
    const float* hidden = (const float*)d_in[0];
    const float* Wq = (const float*)d_in[2];
    const float* Wk = (const float*)d_in[3];
    const float* Wv = (const float*)d_in[4];
    const float* Wo = (const float*)d_in[5];
    float* out = (float*)d_out;

    float* qkv_ptr;
    cudaGetSymbolAddress((void**)&qkv_ptr, g_qkv);

    __half *aHi, *aLo, *bQKV, *bO;
    __half *qH, *qL, *kH, *vtH, *vtL;
    cudaGetSymbolAddress((void**)&aHi, gA_hi);
    cudaGetSymbolAddress((void**)&aLo, gA_lo);
    cudaGetSymbolAddress((void**)&bQKV, gBqkv);
    cudaGetSymbolAddress((void**)&bO, gBo);
    cudaGetSymbolAddress((void**)&qH, gQhi);
    cudaGetSymbolAddress((void**)&qL, gQlo);
    cudaGetSymbolAddress((void**)&kH, gKhi);
    cudaGetSymbolAddress((void**)&vtH, gVThi);
    cudaGetSymbolAddress((void**)&vtL, gVTlo);

    cudaFuncSetAttribute(gemm_fp16x2_kernel, cudaFuncAttributeMaxDynamicSharedMemorySize, GEMM_SMEM);
    cudaFuncSetAttribute(flash_mma_kernel, cudaFuncAttributeMaxDynamicSharedMemorySize, FLASH_SMEM);

    // 1) fused input prep
    input_prep_kernel<<<IN_TOTAL_BLKS, 256>>>(hidden, Wq, Wk, Wv, Wo, aHi, aLo, bQKV, bO);

    // 2) fused QKV projection
    gemm_fp16x2_kernel<<<dim3(NQKV / 128, MROWS / 64), 128, GEMM_SMEM>>>(aHi, aLo, bQKV, qkv_ptr, NQKV);

    // 3) fused prep (rope Q, rope K, V transpose)
    prep_kernel<<<PREP_TOTAL_BLKS, 256>>>(qkv_ptr, qH, qL, kH, vtH, vtL);

    // 4) attention: 64-row q-tiles paired (p, 15-p), 128 threads, occ 4
    {
        dim3 g(NQT64 / 2, BATCH * HQ);
        flash_mma_kernel<<<g, 128, FLASH_SMEM>>>(qH, qL, kH, vtH, vtL, aHi, aLo);
    }

    // 5) output projection
    gemm_fp16x2_kernel<<<dim3(2048 / 128, MROWS / 64), 128, GEMM_SMEM>>>(aHi, aLo, bO, out, 2048);
}

// round 14
// speedup vs baseline: 1.0452x; 1.0419x over previous
#include <cuda_runtime.h>
#include <cuda_fp16.h>
#include <math.h>
#include <stdint.h>

// ---------------- problem constants ----------------
#define BATCH 2
#define SEQ 1024
#define HIDDEN 2048
#define HQ 32
#define HKV 8
#define HD 64
#define MROWS (BATCH * SEQ)     // 2048
#define KDIM HIDDEN             // 2048
#define NQKV 3072
#define NEG_BIG (-1e9f)

// ---------------- scratch ----------------
__device__ float g_qkv[MROWS * NQKV];

__device__ __half gA_hi[MROWS * KDIM];
__device__ __half gA_lo[MROWS * KDIM];
__device__ __half gBqkv[NQKV * KDIM];
__device__ __half gBo[2048 * KDIM];

__device__ __half gQhi[MROWS * HQ * HD];
__device__ __half gQlo[MROWS * HQ * HD];
__device__ __half gKhi[MROWS * HKV * HD];
__device__ __half gVThi[BATCH * HKV * HD * SEQ];

// ---------------- helpers ----------------
__device__ __forceinline__ uint32_t smem_to_u32(const void* p) {
    uint32_t a;
    asm("{ .reg .u64 t; cvta.to.shared.u64 t, %1; cvt.u32.u64 %0, t; }" : "=r"(a) : "l"(p));
    return a;
}
#define LDM4(r0, r1, r2, r3, addr) \
    asm volatile("ldmatrix.sync.aligned.m8n8.x4.shared.b16 {%0,%1,%2,%3}, [%4];" \
        : "=r"(r0), "=r"(r1), "=r"(r2), "=r"(r3) : "r"(addr))

__device__ __forceinline__ void mma16816(float* d, const uint32_t* a, uint32_t b0, uint32_t b1) {
    asm volatile("mma.sync.aligned.m16n8k16.row.col.f32.f16.f16.f32 "
        "{%0,%1,%2,%3}, {%4,%5,%6,%7}, {%8,%9}, {%0,%1,%2,%3};"
        : "+f"(d[0]), "+f"(d[1]), "+f"(d[2]), "+f"(d[3])
        : "r"(a[0]), "r"(a[1]), "r"(a[2]), "r"(a[3]), "r"(b0), "r"(b1));
}
__device__ __forceinline__ uint32_t pack_f16x2(float lo, float hi) {
    uint32_t d;
    asm("cvt.rn.f16x2.f32 %0, %1, %2;" : "=r"(d) : "f"(hi), "f"(lo));
    return d;
}

// ---------------- fp16x2 GEMM (R9 config): 64x128 tile, BK=32, 3 stages, occ 3 ----------------
#define BK 32
#define PITCH 40
#define A_ELEMS (64 * PITCH)
#define B_ELEMS (128 * PITCH)
#define STAGE_ELEMS (2 * A_ELEMS + B_ELEMS)
#define NSTAGE 3
#define GEMM_SMEM (NSTAGE * STAGE_ELEMS * 2)        // 61440 bytes
#define NCHUNK (KDIM / BK)

__device__ __forceinline__ void issue_stage(
    uint32_t sb, int stage,
    const __half* __restrict__ Ahi, const __half* __restrict__ Alo,
    const __half* __restrict__ B,
    int m0, int n0, int k0, int tid)
{
    #pragma unroll
    for (int t = 0; t < 8; t++) {
        int idx = tid + t * 128;
        int ch = idx & 3;
        const __half* src;
        uint32_t dstoff;
        if (idx < 512) {
            int tl = idx >> 8;
            int row = (idx >> 2) & 63;
            src = (tl ? Alo : Ahi) + (size_t)(m0 + row) * KDIM + k0 + ch * 8;
            dstoff = (uint32_t)(tl * A_ELEMS + row * PITCH + ch * 8);
        } else {
            int row = (idx >> 2) & 127;
            src = B + (size_t)(n0 + row) * KDIM + k0 + ch * 8;
            dstoff = (uint32_t)(2 * A_ELEMS + row * PITCH + ch * 8);
        }
        uint32_t dst = sb + 2u * ((uint32_t)stage * STAGE_ELEMS + dstoff);
        asm volatile("cp.async.cg.shared.global [%0], [%1], 16;" :: "r"(dst), "l"(src));
    }
    asm volatile("cp.async.commit_group;");
}

__global__ __launch_bounds__(128, 3) void gemm_fp16x2_kernel(
    const __half* __restrict__ Ahi, const __half* __restrict__ Alo,
    const __half* __restrict__ B,
    float* __restrict__ C, int N)
{
    extern __shared__ char smem[];
    const uint32_t sb = smem_to_u32(smem);
    const int tid = threadIdx.x;
    const int wid = tid >> 5;
    const int lid = tid & 31;
    const int g = lid >> 2;
    const int t4 = lid & 3;
    const int n0 = blockIdx.x * 128;
    const int m0 = blockIdx.y * 64;

    const int arow_l = (lid & 7) + ((lid >> 3) & 1) * 8;
    const int acol_l = (lid >> 4) * 8;
    const int brow_l = (lid & 7) + (lid >> 4) * 8;
    const int bcol_l = ((lid >> 3) & 1) * 8;

    float acc[4][4][4];
    #pragma unroll
    for (int i = 0; i < 4; i++)
        #pragma unroll
        for (int j = 0; j < 4; j++)
            #pragma unroll
            for (int r = 0; r < 4; r++) acc[i][j][r] = 0.f;

    issue_stage(sb, 0, Ahi, Alo, B, m0, n0, 0, tid);
    issue_stage(sb, 1, Ahi, Alo, B, m0, n0, BK, tid);

    int p = 0;
    for (int i = 0; i < NCHUNK; i++) {
        if (i < NCHUNK - 1) {
            asm volatile("cp.async.wait_group 1;" ::: "memory");
        } else {
            asm volatile("cp.async.wait_group 0;" ::: "memory");
        }
        __syncthreads();

        if (i + 2 < NCHUNK) {
            int st = p + 2; if (st >= NSTAGE) st -= NSTAGE;
            issue_stage(sb, st, Ahi, Alo, B, m0, n0, (i + 2) * BK, tid);
        }

        const uint32_t base = sb + 2u * (uint32_t)(p * STAGE_ELEMS);
        #pragma unroll
        for (int ks = 0; ks < 2; ks++) {
            const int kb = ks * 16;
            uint32_t ah[4][4], al[4][4], bb[4][2];
            #pragma unroll
            for (int mt = 0; mt < 4; mt++) {
                uint32_t ad = base + 2u * (uint32_t)((mt * 16 + arow_l) * PITCH + kb + acol_l);
                LDM4(ah[mt][0], ah[mt][1], ah[mt][2], ah[mt][3], ad);
                LDM4(al[mt][0], al[mt][1], al[mt][2], al[mt][3], ad + 2u * A_ELEMS);
            }
            #pragma unroll
            for (int ntp = 0; ntp < 2; ntp++) {
                uint32_t bd = base + 2u * (uint32_t)(2 * A_ELEMS + (wid * 32 + ntp * 16 + brow_l) * PITCH + kb + bcol_l);
                uint32_t r0, r1, r2, r3;
                LDM4(r0, r1, r2, r3, bd);
                bb[2 * ntp][0] = r0; bb[2 * ntp][1] = r1;
                bb[2 * ntp + 1][0] = r2; bb[2 * ntp + 1][1] = r3;
            }
            #pragma unroll
            for (int mt = 0; mt < 4; mt++)
                #pragma unroll
                for (int nt = 0; nt < 4; nt++)
                    mma16816(acc[mt][nt], ah[mt], bb[nt][0], bb[nt][1]);
            #pragma unroll
            for (int mt = 0; mt < 4; mt++)
                #pragma unroll
                for (int nt = 0; nt < 4; nt++)
                    mma16816(acc[mt][nt], al[mt], bb[nt][0], bb[nt][1]);
        }
        if (++p == NSTAGE) p = 0;
    }

    #pragma unroll
    for (int mt = 0; mt < 4; mt++) {
        int row = m0 + mt * 16 + g;
        #pragma unroll
        for (int nt = 0; nt < 4; nt++) {
            int col = n0 + wid * 32 + nt * 8 + 2 * t4;
            *(float2*)&C[(size_t)row * N + col] = make_float2(acc[mt][nt][0], acc[mt][nt][1]);
            *(float2*)&C[(size_t)(row + 8) * N + col] = make_float2(acc[mt][nt][2], acc[mt][nt][3]);
        }
    }
}

// ---------------- fused input prep ----------------
#define ISPLIT_BLKS 4096
#define WT_BLKS (160 * 64)
#define IN_TOTAL_BLKS (ISPLIT_BLKS + WT_BLKS)

__global__ void input_prep_kernel(const float* __restrict__ hidden,
                                  const float* __restrict__ Wq, const float* __restrict__ Wk,
                                  const float* __restrict__ Wv, const float* __restrict__ Wo,
                                  __half* __restrict__ aHi, __half* __restrict__ aLo,
                                  __half* __restrict__ bQKV, __half* __restrict__ bO)
{
    const int blk = blockIdx.x;
    const int tid = threadIdx.x;

    if (blk < ISPLIT_BLKS) {
        int i = blk * 256 + tid;
        float4 v = ((const float4*)hidden)[i];
        __half h0 = __float2half_rn(v.x), h1 = __float2half_rn(v.y);
        __half h2 = __float2half_rn(v.z), h3 = __float2half_rn(v.w);
        uint2 hv, lv;
        hv.x = pack_f16x2(__half2float(h0), __half2float(h1));
        hv.y = pack_f16x2(__half2float(h2), __half2float(h3));
        lv.x = pack_f16x2(v.x - __half2float(h0), v.y - __half2float(h1));
        lv.y = pack_f16x2(v.z - __half2float(h2), v.w - __half2float(h3));
        ((uint2*)aHi)[i] = hv;
        ((uint2*)aLo)[i] = lv;
    } else {
        __shared__ float t[32][33];
        int local = blk - ISPLIT_BLKS;
        const int ntile = local % 160;
        const int k0 = (local / 160) * 32;
        const float* W;  __half* dst;  int N;  int n0;
        if (ntile < 64)      { W = Wq; dst = bQKV;                       N = 2048; n0 = ntile * 32; }
        else if (ntile < 80) { W = Wk; dst = bQKV + (size_t)2048 * KDIM; N = 512;  n0 = (ntile - 64) * 32; }
        else if (ntile < 96) { W = Wv; dst = bQKV + (size_t)2560 * KDIM; N = 512;  n0 = (ntile - 80) * 32; }
        else                 { W = Wo; dst = bO;                         N = 2048; n0 = (ntile - 96) * 32; }

        const int tx = tid & 31, ty = tid >> 5;
        #pragma unroll
        for (int i = 0; i < 32; i += 8)
            t[ty + i][tx] = W[(size_t)(k0 + ty + i) * N + n0 + tx];
        __syncthreads();
        #pragma unroll
        for (int i = 0; i < 32; i += 8) {
            float v = t[tx][ty + i];
            dst[(size_t)(n0 + ty + i) * KDIM + k0 + tx] = __float2half_rn(v);
        }
    }
}

// ---------------- fused prep: rope(Q) | rope(K) | V-transpose (hi only) ----------------
#define PREP_ROPEQ_BLKS 8192
#define PREP_ROPEK_BLKS 2048
#define PREP_VT_BLKS 1024
#define PREP_TOTAL_BLKS (PREP_ROPEQ_BLKS + PREP_ROPEK_BLKS + PREP_VT_BLKS)

__device__ __forceinline__ void rope_body(const float* __restrict__ qkv, int colOff,
                                          __half* __restrict__ hi, __half* __restrict__ lo,
                                          int heads, int idx)
{
    int dpair = idx & 31;
    int t = idx >> 5;
    int h = t % heads;  t /= heads;
    int s = t % SEQ;
    int b = t / SEQ;

    float inv = powf(10000.0f, -(float)(2 * dpair) / (float)HD);
    float ang = (float)s * inv;
    float sn, cs;
    sincosf(ang, &sn, &cs);

    size_t src = ((size_t)b * SEQ + s) * NQKV + colOff + h * HD + dpair;
    float x1 = qkv[src];
    float x2 = qkv[src + HD / 2];
    float y1 = x1 * cs - x2 * sn;
    float y2 = x2 * cs + x1 * sn;

    size_t base = (((size_t)b * SEQ + s) * heads + h) * HD + dpair;
    __half h1 = __float2half_rn(y1);
    __half h2 = __float2half_rn(y2);
    hi[base] = h1;
    hi[base + HD / 2] = h2;
    if (lo) {
        lo[base] = __float2half_rn(y1 - __half2float(h1));
        lo[base + HD / 2] = __float2half_rn(y2 - __half2float(h2));
    }
}

__global__ void prep_kernel(const float* __restrict__ qkv,
                            __half* __restrict__ qH, __half* __restrict__ qL,
                            __half* __restrict__ kH,
                            __half* __restrict__ vtH)
{
    const int blk = blockIdx.x;
    const int tid = threadIdx.x;

    if (blk < PREP_ROPEQ_BLKS) {
        rope_body(qkv, 0, qH, qL, HQ, blk * 256 + tid);
    } else if (blk < PREP_ROPEQ_BLKS + PREP_ROPEK_BLKS) {
        rope_body(qkv, 2048, kH, (__half*)0, HKV, (blk - PREP_ROPEQ_BLKS) * 256 + tid);
    } else {
        __shared__ float t[32][33];
        int local = blk - PREP_ROPEQ_BLKS - PREP_ROPEK_BLKS;
        const int s0 = (local & 31) * 32;
        const int d0 = ((local >> 5) & 1) * 32;
        const int bh = local >> 6;
        const int b = bh >> 3;
        const int h = bh & 7;
        const int tx = tid & 31, ty = tid >> 5;
        #pragma unroll
        for (int i = 0; i < 32; i += 8)
            t[ty + i][tx] = qkv[((size_t)b * SEQ + s0 + ty + i) * NQKV + 2560 + h * HD + d0 + tx];
        __syncthreads();
        #pragma unroll
        for (int i = 0; i < 32; i += 8) {
            float x = t[tx][ty + i];
            size_t o = (((size_t)b * HKV + h) * HD + d0 + ty + i) * SEQ + s0 + tx;
            vtH[o] = __float2half_rn(x);
        }
    }
}

// ---------------- flash: V single-precision, 2-tile KV stages, occ 4 ----------------
#define FPITCH 72
#define QH_OFF 0
#define QL_OFF (64 * FPITCH)
#define KH_OFF 0
#define VH_OFF (64 * FPITCH)
#define KV_STAGE_ELEMS (128 * FPITCH)              // 2 tiles x 64 rows
#define FLASH_SMEM (2 * KV_STAGE_ELEMS * 2)        // 36864 bytes
#define NQT (SEQ / 128)                            // 8 q-tiles of 128 rows

__device__ __forceinline__ void flash_issue_kv(
    uint32_t sb, int stage,
    const __half* __restrict__ khi, const __half* __restrict__ vthi,
    int b, int hkv, int kt, int tid)
{
    #pragma unroll
    for (int it = 0; it < 4; it++) {
        int idx = tid + it * 256;           // 0..1023
        int tile = idx >> 9;
        int r = (idx >> 3) & 63;
        int ch = idx & 7;
        const __half* src;
        int dstoff;
        if (tile == 0) { src = &khi[(((size_t)b * SEQ + kt * 64 + r) * HKV + hkv) * HD + ch * 8]; dstoff = KH_OFF; }
        else { src = &vthi[(((size_t)b * HKV + hkv) * HD + r) * SEQ + kt * 64 + ch * 8]; dstoff = VH_OFF; }
        uint32_t dst = sb + 2u * (uint32_t)(stage * KV_STAGE_ELEMS + dstoff + r * FPITCH + ch * 8);
        asm volatile("cp.async.cg.shared.global [%0], [%1], 16;" :: "r"(dst), "l"(src));
    }
    asm volatile("cp.async.commit_group;");
}

__global__ __launch_bounds__(256, 2) void flash_mma_kernel(
    const __half* __restrict__ qhi, const __half* __restrict__ qlo,
    const __half* __restrict__ khi, const __half* __restrict__ vthi,
    __half* __restrict__ outHi, __half* __restrict__ outLo)
{
    extern __shared__ char smem[];
    const uint32_t sb = smem_to_u32(smem);
    __half* sm = (__half*)smem;

    const int tid = threadIdx.x;
    const int wid = tid >> 5;
    const int lid = tid & 31;
    const int g = lid >> 2;
    const int t4 = lid & 3;
    const int pairIdx = blockIdx.x;      // 0..3
    const int bh = blockIdx.y;
    const int b = bh >> 5;
    const int h = bh & 31;
    const int hkv = h >> 2;

    const int arow_l = (lid & 7) + ((lid >> 3) & 1) * 8;
    const int acol_l = (lid >> 4) * 8;
    const int brow_l = (lid & 7) + (lid >> 4) * 8;
    const int bcol_l = ((lid >> 3) & 1) * 8;

    const float scale = 0.125f;

    #pragma unroll
    for (int half = 0; half < 2; half++) {
        const int qt = half ? (NQT - 1 - pairIdx) : pairIdx;

        // ---- stage Q tile (128 rows: hi at QH_OFF spans stage0, lo at QL_OFF... ----
        // Q hi needs 128 rows * FPITCH; it spans both KV tile slots of stage 0 (OK: overlay).
        // Q lo goes into stage 1's region.
        __syncthreads();
        #pragma unroll
        for (int it = 0; it < 4; it++) {
            int idx = tid + it * 256;
            int row = idx >> 3;
            int ch = idx & 7;
            size_t goff = (((size_t)b * SEQ + qt * 128 + row) * HQ + h) * HD + ch * 8;
            *(uint4*)&sm[row * FPITCH + ch * 8] = *(const uint4*)&qhi[goff];
            *(uint4*)&sm[KV_STAGE_ELEMS + row * FPITCH + ch * 8] = *(const uint4*)&qlo[goff];
        }
        __syncthreads();

        uint32_t qh[4][4], ql[4][4];
        #pragma unroll
        for (int ks = 0; ks < 4; ks++) {
            uint32_t ad = sb + 2u * (uint32_t)((wid * 16 + arow_l) * FPITCH + ks * 16 + acol_l);
            LDM4(qh[ks][0], qh[ks][1], qh[ks][2], qh[ks][3], ad);
            ad = sb + 2u * (uint32_t)(KV_STAGE_ELEMS + (wid * 16 + arow_l) * FPITCH + ks * 16 + acol_l);
            LDM4(ql[ks][0], ql[ks][1], ql[ks][2], ql[ks][3], ad);
        }
        __syncthreads();

        float m0 = -1e30f, m1 = -1e30f, l0 = 0.f, l1 = 0.f;
        float oacc[8][4];
        #pragma unroll
        for (int nt = 0; nt < 8; nt++)
            #pragma unroll
            for (int r = 0; r < 4; r++) oacc[nt][r] = 0.f;

        const int row0 = qt * 128 + wid * 16;
        const int r_g = row0 + g;
        const int r_g8 = r_g + 8;
        const int nkt = 2 * qt + 2;

        flash_issue_kv(sb, 0, khi, vthi, b, hkv, 0, tid);

        for (int kt = 0; kt < nkt; kt++) {
            const int stg = kt & 1;
            if (kt + 1 < nkt) {
                flash_issue_kv(sb, 1 - stg, khi, vthi, b, hkv, kt + 1, tid);
                asm volatile("cp.async.wait_group 1;" ::: "memory");
            } else {
                asm volatile("cp.async.wait_group 0;" ::: "memory");
            }
            __syncthreads();

            const uint32_t kvb = sb + 2u * (uint32_t)(stg * KV_STAGE_ELEMS);

            float sacc[8][4];
            #pragma unroll
            for (int nt = 0; nt < 8; nt++)
                #pragma unroll
                for (int r = 0; r < 4; r++) sacc[nt][r] = 0.f;

            #pragma unroll
            for (int ks = 0; ks < 4; ks++) {
                uint32_t kf[4][4];
                #pragma unroll
                for (int ntp = 0; ntp < 4; ntp++) {
                    uint32_t bd = kvb + 2u * (uint32_t)(KH_OFF + (ntp * 16 + brow_l) * FPITCH + ks * 16 + bcol_l);
                    LDM4(kf[ntp][0], kf[ntp][1], kf[ntp][2], kf[ntp][3], bd);
                }
                #pragma unroll
                for (int ntp = 0; ntp < 4; ntp++) {
                    mma16816(sacc[2 * ntp],     qh[ks], kf[ntp][0], kf[ntp][1]);
                    mma16816(sacc[2 * ntp + 1], qh[ks], kf[ntp][2], kf[ntp][3]);
                }
                #pragma unroll
                for (int ntp = 0; ntp < 4; ntp++) {
                    mma16816(sacc[2 * ntp],     ql[ks], kf[ntp][0], kf[ntp][1]);
                    mma16816(sacc[2 * ntp + 1], ql[ks], kf[ntp][2], kf[ntp][3]);
                }
            }

            const bool maybe_mask = (kt * 64 + 63 > row0);
            float mx0 = -1e30f, mx1 = -1e30f;
            #pragma unroll
            for (int nt = 0; nt < 8; nt++) {
                #pragma unroll
                for (int r = 0; r < 4; r++) sacc[nt][r] *= scale;
                if (maybe_mask) {
                    int colb = kt * 64 + nt * 8 + 2 * t4;
                    if (colb > r_g)      sacc[nt][0] = NEG_BIG;
                    if (colb + 1 > r_g)  sacc[nt][1] = NEG_BIG;
                    if (colb > r_g8)     sacc[nt][2] = NEG_BIG;
                    if (colb + 1 > r_g8) sacc[nt][3] = NEG_BIG;
                }
                mx0 = fmaxf(mx0, fmaxf(sacc[nt][0], sacc[nt][1]));
                mx1 = fmaxf(mx1, fmaxf(sacc[nt][2], sacc[nt][3]));
            }
            mx0 = fmaxf(mx0, __shfl_xor_sync(0xffffffffu, mx0, 1));
            mx0 = fmaxf(mx0, __shfl_xor_sync(0xffffffffu, mx0, 2));
            mx1 = fmaxf(mx1, __shfl_xor_sync(0xffffffffu, mx1, 1));
            mx1 = fmaxf(mx1, __shfl_xor_sync(0xffffffffu, mx1, 2));

            float mn0 = fmaxf(m0, mx0), mn1 = fmaxf(m1, mx1);
            float corr0 = __expf(m0 - mn0), corr1 = __expf(m1 - mn1);

            uint32_t ph[8][2];
            float rs0 = 0.f, rs1 = 0.f;
            #pragma unroll
            for (int nt = 0; nt < 8; nt++) {
                float p00 = __expf(sacc[nt][0] - mn0);
                float p01 = __expf(sacc[nt][1] - mn0);
                float p10 = __expf(sacc[nt][2] - mn1);
                float p11 = __expf(sacc[nt][3] - mn1);
                rs0 += p00 + p01;
                rs1 += p10 + p11;
                ph[nt][0] = pack_f16x2(p00, p01);
                ph[nt][1] = pack_f16x2(p10, p11);
            }
            rs0 += __shfl_xor_sync(0xffffffffu, rs0, 1);
            rs0 += __shfl_xor_sync(0xffffffffu, rs0, 2);
            rs1 += __shfl_xor_sync(0xffffffffu, rs1, 1);
            rs1 += __shfl_xor_sync(0xffffffffu, rs1, 2);

            l0 = l0 * corr0 + rs0;
            l1 = l1 * corr1 + rs1;
            m0 = mn0; m1 = mn1;
            #pragma unroll
            for (int nt = 0; nt < 8; nt++) {
                oacc[nt][0] *= corr0; oacc[nt][1] *= corr0;
                oacc[nt][2] *= corr1; oacc[nt][3] *= corr1;
            }

            #pragma unroll
            for (int ks = 0; ks < 4; ks++) {
                uint32_t pah[4] = { ph[2 * ks][0], ph[2 * ks][1], ph[2 * ks + 1][0], ph[2 * ks + 1][1] };
                uint32_t vfh[4][4];
                #pragma unroll
                for (int ntp = 0; ntp < 4; ntp++) {
                    uint32_t bd = kvb + 2u * (uint32_t)(VH_OFF + (ntp * 16 + brow_l) * FPITCH + ks * 16 + bcol_l);
                    LDM4(vfh[ntp][0], vfh[ntp][1], vfh[ntp][2], vfh[ntp][3], bd);
                }
                #pragma unroll
                for (int ntp = 0; ntp < 4; ntp++) {
                    mma16816(oacc[2 * ntp],     pah, vfh[ntp][0], vfh[ntp][1]);
                    mma16816(oacc[2 * ntp + 1], pah, vfh[ntp][2], vfh[ntp][3]);
                }
            }
            __syncthreads();
        }

        // ---- epilogue ----
        float inv0 = 1.0f / l0, inv1 = 1.0f / l1;
        uint32_t* oHi = (uint32_t*)outHi;
        uint32_t* oLo = (uint32_t*)outLo;
        #pragma unroll
        for (int nt = 0; nt < 8; nt++) {
            float o00 = oacc[nt][0] * inv0, o01 = oacc[nt][1] * inv0;
            float o10 = oacc[nt][2] * inv1, o11 = oacc[nt][3] * inv1;
            float h00 = __half2float(__float2half_rn(o00));
            float h01 = __half2float(__float2half_rn(o01));
            float h10 = __half2float(__float2half_rn(o10));
            float h11 = __half2float(__float2half_rn(o11));
            size_t row = (size_t)b * SEQ + qt * 128 + wid * 16 + g;
            int col = h * 64 + nt * 8 + 2 * t4;
            oHi[(row * 2048 + col) >> 1] = pack_f16x2(h00, h01);
            oLo[(row * 2048 + col) >> 1] = pack_f16x2(o00 - h00, o01 - h01);
            oHi[((row + 8) * 2048 + col) >> 1] = pack_f16x2(h10, h11);
            oLo[((row + 8) * 2048 + col) >> 1] = pack_f16x2(o10 - h10, o11 - h11);
        }
    }
}

// ---------------- launcher ----------------
extern "C" void kernel_launch(void* const* d_in, const int* in_sizes, int n_in,
                              void* d_out, int out_size)
{
    const float* hidden = (const float*)d_in[0];
    const float* Wq = (const float*)d_in[2];
    const float* Wk = (const float*)d_in[3];
    const float* Wv = (const float*)d_in[4];
    const float* Wo = (const float*)d_in[5];
    float* out = (float*)d_out;

    float* qkv_ptr;
    cudaGetSymbolAddress((void**)&qkv_ptr, g_qkv);

    __half *aHi, *aLo, *bQKV, *bO;
    __half *qH, *qL, *kH, *vtH;
    cudaGetSymbolAddress((void**)&aHi, gA_hi);
    cudaGetSymbolAddress((void**)&aLo, gA_lo);
    cudaGetSymbolAddress((void**)&bQKV, gBqkv);
    cudaGetSymbolAddress((void**)&bO, gBo);
    cudaGetSymbolAddress((void**)&qH, gQhi);
    cudaGetSymbolAddress((void**)&qL, gQlo);
    cudaGetSymbolAddress((void**)&kH, gKhi);
    cudaGetSymbolAddress((void**)&vtH, gVThi);

    cudaFuncSetAttribute(gemm_fp16x2_kernel, cudaFuncAttributeMaxDynamicSharedMemorySize, GEMM_SMEM);
    cudaFuncSetAttribute(flash_mma_kernel, cudaFuncAttributeMaxDynamicSharedMemorySize, FLASH_SMEM);

    // 1) fused input prep
    input_prep_kernel<<<IN_TOTAL_BLKS, 256>>>(hidden, Wq, Wk, Wv, Wo, aHi, aLo, bQKV, bO);

    // 2) fused QKV projection
    gemm_fp16x2_kernel<<<dim3(NQKV / 128, MROWS / 64), 128, GEMM_SMEM>>>(aHi, aLo, bQKV, qkv_ptr, NQKV);

    // 3) fused prep (rope Q, rope K, V transpose hi-only)
    prep_kernel<<<PREP_TOTAL_BLKS, 256>>>(qkv_ptr, qH, qL, kH, vtH);

    // 4) attention (paired 128-row q-tiles, V single precision)
    {
        dim3 g(NQT / 2, BATCH * HQ);
        flash_mma_kernel<<<g, 256, FLASH_SMEM>>>(qH, qL, kH, vtH, aHi, aLo);
    }

    // 5) output projection
    gemm_fp16x2_kernel<<<dim3(2048 / 128, MROWS / 64), 128, GEMM_SMEM>>>(aHi, aLo, bO, out, 2048);
}

// round 15
// speedup vs baseline: 1.2019x; 1.1499x over previous
#include <cuda_runtime.h>
#include <cuda_fp16.h>
#include <math.h>
#include <stdint.h>

// ---------------- problem constants ----------------
#define BATCH 2
#define SEQ 1024
#define HIDDEN 2048
#define HQ 32
#define HKV 8
#define HD 64
#define MROWS (BATCH * SEQ)     // 2048
#define KDIM HIDDEN             // 2048
#define NQKV 3072
#define NEG_BIG (-1e9f)

// ---------------- scratch ----------------
__device__ float g_qkv[MROWS * NQKV];

__device__ __half gA_hi[MROWS * KDIM];
__device__ __half gA_lo[MROWS * KDIM];
__device__ __half gBqkv[NQKV * KDIM];
__device__ __half gBo[2048 * KDIM];

__device__ __half gQhi[MROWS * HQ * HD];
__device__ __half gQlo[MROWS * HQ * HD];
__device__ __half gKhi[MROWS * HKV * HD];
__device__ __half gVThi[BATCH * HKV * HD * SEQ];

// ---------------- helpers ----------------
__device__ __forceinline__ uint32_t smem_to_u32(const void* p) {
    uint32_t a;
    asm("{ .reg .u64 t; cvta.to.shared.u64 t, %1; cvt.u32.u64 %0, t; }" : "=r"(a) : "l"(p));
    return a;
}
#define LDM4(r0, r1, r2, r3, addr) \
    asm volatile("ldmatrix.sync.aligned.m8n8.x4.shared.b16 {%0,%1,%2,%3}, [%4];" \
        : "=r"(r0), "=r"(r1), "=r"(r2), "=r"(r3) : "r"(addr))

__device__ __forceinline__ void mma16816(float* d, const uint32_t* a, uint32_t b0, uint32_t b1) {
    asm volatile("mma.sync.aligned.m16n8k16.row.col.f32.f16.f16.f32 "
        "{%0,%1,%2,%3}, {%4,%5,%6,%7}, {%8,%9}, {%0,%1,%2,%3};"
        : "+f"(d[0]), "+f"(d[1]), "+f"(d[2]), "+f"(d[3])
        : "r"(a[0]), "r"(a[1]), "r"(a[2]), "r"(a[3]), "r"(b0), "r"(b1));
}
__device__ __forceinline__ uint32_t pack_f16x2(float lo, float hi) {
    uint32_t d;
    asm("cvt.rn.f16x2.f32 %0, %1, %2;" : "=r"(d) : "f"(hi), "f"(lo));
    return d;
}

// ---------------- fp16x2 GEMM (hi+lo A): 64x128 tile, BK=32, 3 stages, occ 3 ----------------
#define BK 32
#define PITCH 40
#define A_ELEMS (64 * PITCH)
#define B_ELEMS (128 * PITCH)
#define STAGE_ELEMS (2 * A_ELEMS + B_ELEMS)
#define NSTAGE 3
#define GEMM_SMEM (NSTAGE * STAGE_ELEMS * 2)        // 61440 bytes
#define NCHUNK (KDIM / BK)

__device__ __forceinline__ void issue_stage(
    uint32_t sb, int stage,
    const __half* __restrict__ Ahi, const __half* __restrict__ Alo,
    const __half* __restrict__ B,
    int m0, int n0, int k0, int tid)
{
    #pragma unroll
    for (int t = 0; t < 8; t++) {
        int idx = tid + t * 128;
        int ch = idx & 3;
        const __half* src;
        uint32_t dstoff;
        if (idx < 512) {
            int tl = idx >> 8;
            int row = (idx >> 2) & 63;
            src = (tl ? Alo : Ahi) + (size_t)(m0 + row) * KDIM + k0 + ch * 8;
            dstoff = (uint32_t)(tl * A_ELEMS + row * PITCH + ch * 8);
        } else {
            int row = (idx >> 2) & 127;
            src = B + (size_t)(n0 + row) * KDIM + k0 + ch * 8;
            dstoff = (uint32_t)(2 * A_ELEMS + row * PITCH + ch * 8);
        }
        uint32_t dst = sb + 2u * ((uint32_t)stage * STAGE_ELEMS + dstoff);
        asm volatile("cp.async.cg.shared.global [%0], [%1], 16;" :: "r"(dst), "l"(src));
    }
    asm volatile("cp.async.commit_group;");
}

__global__ __launch_bounds__(128, 3) void gemm_fp16x2_kernel(
    const __half* __restrict__ Ahi, const __half* __restrict__ Alo,
    const __half* __restrict__ B,
    float* __restrict__ C, int N)
{
    extern __shared__ char smem[];
    const uint32_t sb = smem_to_u32(smem);
    const int tid = threadIdx.x;
    const int wid = tid >> 5;
    const int lid = tid & 31;
    const int g = lid >> 2;
    const int t4 = lid & 3;
    const int n0 = blockIdx.x * 128;
    const int m0 = blockIdx.y * 64;

    const int arow_l = (lid & 7) + ((lid >> 3) & 1) * 8;
    const int acol_l = (lid >> 4) * 8;
    const int brow_l = (lid & 7) + (lid >> 4) * 8;
    const int bcol_l = ((lid >> 3) & 1) * 8;

    float acc[4][4][4];
    #pragma unroll
    for (int i = 0; i < 4; i++)
        #pragma unroll
        for (int j = 0; j < 4; j++)
            #pragma unroll
            for (int r = 0; r < 4; r++) acc[i][j][r] = 0.f;

    issue_stage(sb, 0, Ahi, Alo, B, m0, n0, 0, tid);
    issue_stage(sb, 1, Ahi, Alo, B, m0, n0, BK, tid);

    int p = 0;
    for (int i = 0; i < NCHUNK; i++) {
        if (i < NCHUNK - 1) {
            asm volatile("cp.async.wait_group 1;" ::: "memory");
        } else {
            asm volatile("cp.async.wait_group 0;" ::: "memory");
        }
        __syncthreads();

        if (i + 2 < NCHUNK) {
            int st = p + 2; if (st >= NSTAGE) st -= NSTAGE;
            issue_stage(sb, st, Ahi, Alo, B, m0, n0, (i + 2) * BK, tid);
        }

        const uint32_t base = sb + 2u * (uint32_t)(p * STAGE_ELEMS);
        #pragma unroll
        for (int ks = 0; ks < 2; ks++) {
            const int kb = ks * 16;
            uint32_t ah[4][4], al[4][4], bb[4][2];
            #pragma unroll
            for (int mt = 0; mt < 4; mt++) {
                uint32_t ad = base + 2u * (uint32_t)((mt * 16 + arow_l) * PITCH + kb + acol_l);
                LDM4(ah[mt][0], ah[mt][1], ah[mt][2], ah[mt][3], ad);
                LDM4(al[mt][0], al[mt][1], al[mt][2], al[mt][3], ad + 2u * A_ELEMS);
            }
            #pragma unroll
            for (int ntp = 0; ntp < 2; ntp++) {
                uint32_t bd = base + 2u * (uint32_t)(2 * A_ELEMS + (wid * 32 + ntp * 16 + brow_l) * PITCH + kb + bcol_l);
                uint32_t r0, r1, r2, r3;
                LDM4(r0, r1, r2, r3, bd);
                bb[2 * ntp][0] = r0; bb[2 * ntp][1] = r1;
                bb[2 * ntp + 1][0] = r2; bb[2 * ntp + 1][1] = r3;
            }
            #pragma unroll
            for (int mt = 0; mt < 4; mt++)
                #pragma unroll
                for (int nt = 0; nt < 4; nt++)
                    mma16816(acc[mt][nt], ah[mt], bb[nt][0], bb[nt][1]);
            #pragma unroll
            for (int mt = 0; mt < 4; mt++)
                #pragma unroll
                for (int nt = 0; nt < 4; nt++)
                    mma16816(acc[mt][nt], al[mt], bb[nt][0], bb[nt][1]);
        }
        if (++p == NSTAGE) p = 0;
    }

    #pragma unroll
    for (int mt = 0; mt < 4; mt++) {
        int row = m0 + mt * 16 + g;
        #pragma unroll
        for (int nt = 0; nt < 4; nt++) {
            int col = n0 + wid * 32 + nt * 8 + 2 * t4;
            *(float2*)&C[(size_t)row * N + col] = make_float2(acc[mt][nt][0], acc[mt][nt][1]);
            *(float2*)&C[(size_t)(row + 8) * N + col] = make_float2(acc[mt][nt][2], acc[mt][nt][3]);
        }
    }
}

// ---------------- fp16x1 GEMM (single A): 64x128 tile, BK=32, 3 stages, occ 4 ----------------
#define STAGE1_ELEMS (A_ELEMS + B_ELEMS)            // 7680 elems = 15360 B
#define GEMM1_SMEM (NSTAGE * STAGE1_ELEMS * 2)      // 46080 bytes

__device__ __forceinline__ void issue_stage_x1(
    uint32_t sb, int stage,
    const __half* __restrict__ A, const __half* __restrict__ B,
    int m0, int n0, int k0, int tid)
{
    #pragma unroll
    for (int t = 0; t < 6; t++) {
        int idx = tid + t * 128;            // 0..767
        int ch = idx & 3;
        const __half* src;
        uint32_t dstoff;
        if (idx < 256) {
            int row = (idx >> 2) & 63;
            src = A + (size_t)(m0 + row) * KDIM + k0 + ch * 8;
            dstoff = (uint32_t)(row * PITCH + ch * 8);
        } else {
            int row = ((idx - 256) >> 2) & 127;
            src = B + (size_t)(n0 + row) * KDIM + k0 + ch * 8;
            dstoff = (uint32_t)(A_ELEMS + row * PITCH + ch * 8);
        }
        uint32_t dst = sb + 2u * ((uint32_t)stage * STAGE1_ELEMS + dstoff);
        asm volatile("cp.async.cg.shared.global [%0], [%1], 16;" :: "r"(dst), "l"(src));
    }
    asm volatile("cp.async.commit_group;");
}

__global__ __launch_bounds__(128, 4) void gemm_fp16x1_kernel(
    const __half* __restrict__ A, const __half* __restrict__ B,
    float* __restrict__ C, int N)
{
    extern __shared__ char smem[];
    const uint32_t sb = smem_to_u32(smem);
    const int tid = threadIdx.x;
    const int wid = tid >> 5;
    const int lid = tid & 31;
    const int g = lid >> 2;
    const int t4 = lid & 3;
    const int n0 = blockIdx.x * 128;
    const int m0 = blockIdx.y * 64;

    const int arow_l = (lid & 7) + ((lid >> 3) & 1) * 8;
    const int acol_l = (lid >> 4) * 8;
    const int brow_l = (lid & 7) + (lid >> 4) * 8;
    const int bcol_l = ((lid >> 3) & 1) * 8;

    float acc[4][4][4];
    #pragma unroll
    for (int i = 0; i < 4; i++)
        #pragma unroll
        for (int j = 0; j < 4; j++)
            #pragma unroll
            for (int r = 0; r < 4; r++) acc[i][j][r] = 0.f;

    issue_stage_x1(sb, 0, A, B, m0, n0, 0, tid);
    issue_stage_x1(sb, 1, A, B, m0, n0, BK, tid);

    int p = 0;
    for (int i = 0; i < NCHUNK; i++) {
        if (i < NCHUNK - 1) {
            asm volatile("cp.async.wait_group 1;" ::: "memory");
        } else {
            asm volatile("cp.async.wait_group 0;" ::: "memory");
        }
        __syncthreads();

        if (i + 2 < NCHUNK) {
            int st = p + 2; if (st >= NSTAGE) st -= NSTAGE;
            issue_stage_x1(sb, st, A, B, m0, n0, (i + 2) * BK, tid);
        }

        const uint32_t base = sb + 2u * (uint32_t)(p * STAGE1_ELEMS);
        #pragma unroll
        for (int ks = 0; ks < 2; ks++) {
            const int kb = ks * 16;
            uint32_t ah[4][4], bb[4][2];
            #pragma unroll
            for (int mt = 0; mt < 4; mt++) {
                uint32_t ad = base + 2u * (uint32_t)((mt * 16 + arow_l) * PITCH + kb + acol_l);
                LDM4(ah[mt][0], ah[mt][1], ah[mt][2], ah[mt][3], ad);
            }
            #pragma unroll
            for (int ntp = 0; ntp < 2; ntp++) {
                uint32_t bd = base + 2u * (uint32_t)(A_ELEMS + (wid * 32 + ntp * 16 + brow_l) * PITCH + kb + bcol_l);
                uint32_t r0, r1, r2, r3;
                LDM4(r0, r1, r2, r3, bd);
                bb[2 * ntp][0] = r0; bb[2 * ntp][1] = r1;
                bb[2 * ntp + 1][0] = r2; bb[2 * ntp + 1][1] = r3;
            }
            #pragma unroll
            for (int mt = 0; mt < 4; mt++)
                #pragma unroll
                for (int nt = 0; nt < 4; nt++)
                    mma16816(acc[mt][nt], ah[mt], bb[nt][0], bb[nt][1]);
        }
        if (++p == NSTAGE) p = 0;
    }

    #pragma unroll
    for (int mt = 0; mt < 4; mt++) {
        int row = m0 + mt * 16 + g;
        #pragma unroll
        for (int nt = 0; nt < 4; nt++) {
            int col = n0 + wid * 32 + nt * 8 + 2 * t4;
            *(float2*)&C[(size_t)row * N + col] = make_float2(acc[mt][nt][0], acc[mt][nt][1]);
            *(float2*)&C[(size_t)(row + 8) * N + col] = make_float2(acc[mt][nt][2], acc[mt][nt][3]);
        }
    }
}

// ---------------- fused input prep ----------------
#define ISPLIT_BLKS 4096
#define WT_BLKS (160 * 64)
#define IN_TOTAL_BLKS (ISPLIT_BLKS + WT_BLKS)

__global__ void input_prep_kernel(const float* __restrict__ hidden,
                                  const float* __restrict__ Wq, const float* __restrict__ Wk,
                                  const float* __restrict__ Wv, const float* __restrict__ Wo,
                                  __half* __restrict__ aHi, __half* __restrict__ aLo,
                                  __half* __restrict__ bQKV, __half* __restrict__ bO)
{
    const int blk = blockIdx.x;
    const int tid = threadIdx.x;

    if (blk < ISPLIT_BLKS) {
        int i = blk * 256 + tid;
        float4 v = ((const float4*)hidden)[i];
        __half h0 = __float2half_rn(v.x), h1 = __float2half_rn(v.y);
        __half h2 = __float2half_rn(v.z), h3 = __float2half_rn(v.w);
        uint2 hv, lv;
        hv.x = pack_f16x2(__half2float(h0), __half2float(h1));
        hv.y = pack_f16x2(__half2float(h2), __half2float(h3));
        lv.x = pack_f16x2(v.x - __half2float(h0), v.y - __half2float(h1));
        lv.y = pack_f16x2(v.z - __half2float(h2), v.w - __half2float(h3));
        ((uint2*)aHi)[i] = hv;
        ((uint2*)aLo)[i] = lv;
    } else {
        __shared__ float t[32][33];
        int local = blk - ISPLIT_BLKS;
        const int ntile = local % 160;
        const int k0 = (local / 160) * 32;
        const float* W;  __half* dst;  int N;  int n0;
        if (ntile < 64)      { W = Wq; dst = bQKV;                       N = 2048; n0 = ntile * 32; }
        else if (ntile < 80) { W = Wk; dst = bQKV + (size_t)2048 * KDIM; N = 512;  n0 = (ntile - 64) * 32; }
        else if (ntile < 96) { W = Wv; dst = bQKV + (size_t)2560 * KDIM; N = 512;  n0 = (ntile - 80) * 32; }
        else                 { W = Wo; dst = bO;                         N = 2048; n0 = (ntile - 96) * 32; }

        const int tx = tid & 31, ty = tid >> 5;
        #pragma unroll
        for (int i = 0; i < 32; i += 8)
            t[ty + i][tx] = W[(size_t)(k0 + ty + i) * N + n0 + tx];
        __syncthreads();
        #pragma unroll
        for (int i = 0; i < 32; i += 8) {
            float v = t[tx][ty + i];
            dst[(size_t)(n0 + ty + i) * KDIM + k0 + tx] = __float2half_rn(v);
        }
    }
}

// ---------------- fused prep: rope(Q) | rope(K) | V-transpose (hi only) ----------------
#define PREP_ROPEQ_BLKS 8192
#define PREP_ROPEK_BLKS 2048
#define PREP_VT_BLKS 1024
#define PREP_TOTAL_BLKS (PREP_ROPEQ_BLKS + PREP_ROPEK_BLKS + PREP_VT_BLKS)

__device__ __forceinline__ void rope_body(const float* __restrict__ qkv, int colOff,
                                          __half* __restrict__ hi, __half* __restrict__ lo,
                                          int heads, int idx)
{
    int dpair = idx & 31;
    int t = idx >> 5;
    int h = t % heads;  t /= heads;
    int s = t % SEQ;
    int b = t / SEQ;

    float inv = powf(10000.0f, -(float)(2 * dpair) / (float)HD);
    float ang = (float)s * inv;
    float sn, cs;
    sincosf(ang, &sn, &cs);

    size_t src = ((size_t)b * SEQ + s) * NQKV + colOff + h * HD + dpair;
    float x1 = qkv[src];
    float x2 = qkv[src + HD / 2];
    float y1 = x1 * cs - x2 * sn;
    float y2 = x2 * cs + x1 * sn;

    size_t base = (((size_t)b * SEQ + s) * heads + h) * HD + dpair;
    __half h1 = __float2half_rn(y1);
    __half h2 = __float2half_rn(y2);
    hi[base] = h1;
    hi[base + HD / 2] = h2;
    if (lo) {
        lo[base] = __float2half_rn(y1 - __half2float(h1));
        lo[base + HD / 2] = __float2half_rn(y2 - __half2float(h2));
    }
}

__global__ void prep_kernel(const float* __restrict__ qkv,
                            __half* __restrict__ qH, __half* __restrict__ qL,
                            __half* __restrict__ kH,
                            __half* __restrict__ vtH)
{
    const int blk = blockIdx.x;
    const int tid = threadIdx.x;

    if (blk < PREP_ROPEQ_BLKS) {
        rope_body(qkv, 0, qH, qL, HQ, blk * 256 + tid);
    } else if (blk < PREP_ROPEQ_BLKS + PREP_ROPEK_BLKS) {
        rope_body(qkv, 2048, kH, (__half*)0, HKV, (blk - PREP_ROPEQ_BLKS) * 256 + tid);
    } else {
        __shared__ float t[32][33];
        int local = blk - PREP_ROPEQ_BLKS - PREP_ROPEK_BLKS;
        const int s0 = (local & 31) * 32;
        const int d0 = ((local >> 5) & 1) * 32;
        const int bh = local >> 6;
        const int b = bh >> 3;
        const int h = bh & 7;
        const int tx = tid & 31, ty = tid >> 5;
        #pragma unroll
        for (int i = 0; i < 32; i += 8)
            t[ty + i][tx] = qkv[((size_t)b * SEQ + s0 + ty + i) * NQKV + 2560 + h * HD + d0 + tx];
        __syncthreads();
        #pragma unroll
        for (int i = 0; i < 32; i += 8) {
            float x = t[tx][ty + i];
            size_t o = (((size_t)b * HKV + h) * HD + d0 + ty + i) * SEQ + s0 + tx;
            vtH[o] = __float2half_rn(x);
        }
    }
}

// ---------------- flash: V single-precision, 2-tile KV stages (R14 config) ----------------
#define FPITCH 72
#define KH_OFF 0
#define VH_OFF (64 * FPITCH)
#define KV_STAGE_ELEMS (128 * FPITCH)
#define FLASH_SMEM (2 * KV_STAGE_ELEMS * 2)        // 36864 bytes
#define NQT (SEQ / 128)

__device__ __forceinline__ void flash_issue_kv(
    uint32_t sb, int stage,
    const __half* __restrict__ khi, const __half* __restrict__ vthi,
    int b, int hkv, int kt, int tid)
{
    #pragma unroll
    for (int it = 0; it < 4; it++) {
        int idx = tid + it * 256;
        int tile = idx >> 9;
        int r = (idx >> 3) & 63;
        int ch = idx & 7;
        const __half* src;
        int dstoff;
        if (tile == 0) { src = &khi[(((size_t)b * SEQ + kt * 64 + r) * HKV + hkv) * HD + ch * 8]; dstoff = KH_OFF; }
        else { src = &vthi[(((size_t)b * HKV + hkv) * HD + r) * SEQ + kt * 64 + ch * 8]; dstoff = VH_OFF; }
        uint32_t dst = sb + 2u * (uint32_t)(stage * KV_STAGE_ELEMS + dstoff + r * FPITCH + ch * 8);
        asm volatile("cp.async.cg.shared.global [%0], [%1], 16;" :: "r"(dst), "l"(src));
    }
    asm volatile("cp.async.commit_group;");
}

__global__ __launch_bounds__(256, 2) void flash_mma_kernel(
    const __half* __restrict__ qhi, const __half* __restrict__ qlo,
    const __half* __restrict__ khi, const __half* __restrict__ vthi,
    __half* __restrict__ outHi, __half* __restrict__ outLo)
{
    extern __shared__ char smem[];
    const uint32_t sb = smem_to_u32(smem);
    __half* sm = (__half*)smem;

    const int tid = threadIdx.x;
    const int wid = tid >> 5;
    const int lid = tid & 31;
    const int g = lid >> 2;
    const int t4 = lid & 3;
    const int pairIdx = blockIdx.x;
    const int bh = blockIdx.y;
    const int b = bh >> 5;
    const int h = bh & 31;
    const int hkv = h >> 2;

    const int arow_l = (lid & 7) + ((lid >> 3) & 1) * 8;
    const int acol_l = (lid >> 4) * 8;
    const int brow_l = (lid & 7) + (lid >> 4) * 8;
    const int bcol_l = ((lid >> 3) & 1) * 8;

    const float scale = 0.125f;

    #pragma unroll
    for (int half = 0; half < 2; half++) {
        const int qt = half ? (NQT - 1 - pairIdx) : pairIdx;

        __syncthreads();
        #pragma unroll
        for (int it = 0; it < 4; it++) {
            int idx = tid + it * 256;
            int row = idx >> 3;
            int ch = idx & 7;
            size_t goff = (((size_t)b * SEQ + qt * 128 + row) * HQ + h) * HD + ch * 8;
            *(uint4*)&sm[row * FPITCH + ch * 8] = *(const uint4*)&qhi[goff];
            *(uint4*)&sm[KV_STAGE_ELEMS + row * FPITCH + ch * 8] = *(const uint4*)&qlo[goff];
        }
        __syncthreads();

        uint32_t qh[4][4], ql[4][4];
        #pragma unroll
        for (int ks = 0; ks < 4; ks++) {
            uint32_t ad = sb + 2u * (uint32_t)((wid * 16 + arow_l) * FPITCH + ks * 16 + acol_l);
            LDM4(qh[ks][0], qh[ks][1], qh[ks][2], qh[ks][3], ad);
            ad = sb + 2u * (uint32_t)(KV_STAGE_ELEMS + (wid * 16 + arow_l) * FPITCH + ks * 16 + acol_l);
            LDM4(ql[ks][0], ql[ks][1], ql[ks][2], ql[ks][3], ad);
        }
        __syncthreads();

        float m0 = -1e30f, m1 = -1e30f, l0 = 0.f, l1 = 0.f;
        float oacc[8][4];
        #pragma unroll
        for (int nt = 0; nt < 8; nt++)
            #pragma unroll
            for (int r = 0; r < 4; r++) oacc[nt][r] = 0.f;

        const int row0 = qt * 128 + wid * 16;
        const int r_g = row0 + g;
        const int r_g8 = r_g + 8;
        const int nkt = 2 * qt + 2;

        flash_issue_kv(sb, 0, khi, vthi, b, hkv, 0, tid);

        for (int kt = 0; kt < nkt; kt++) {
            const int stg = kt & 1;
            if (kt + 1 < nkt) {
                flash_issue_kv(sb, 1 - stg, khi, vthi, b, hkv, kt + 1, tid);
                asm volatile("cp.async.wait_group 1;" ::: "memory");
            } else {
                asm volatile("cp.async.wait_group 0;" ::: "memory");
            }
            __syncthreads();

            const uint32_t kvb = sb + 2u * (uint32_t)(stg * KV_STAGE_ELEMS);

            float sacc[8][4];
            #pragma unroll
            for (int nt = 0; nt < 8; nt++)
                #pragma unroll
                for (int r = 0; r < 4; r++) sacc[nt][r] = 0.f;

            #pragma unroll
            for (int ks = 0; ks < 4; ks++) {
                uint32_t kf[4][4];
                #pragma unroll
                for (int ntp = 0; ntp < 4; ntp++) {
                    uint32_t bd = kvb + 2u * (uint32_t)(KH_OFF + (ntp * 16 + brow_l) * FPITCH + ks * 16 + bcol_l);
                    LDM4(kf[ntp][0], kf[ntp][1], kf[ntp][2], kf[ntp][3], bd);
                }
                #pragma unroll
                for (int ntp = 0; ntp < 4; ntp++) {
                    mma16816(sacc[2 * ntp],     qh[ks], kf[ntp][0], kf[ntp][1]);
                    mma16816(sacc[2 * ntp + 1], qh[ks], kf[ntp][2], kf[ntp][3]);
                }
                #pragma unroll
                for (int ntp = 0; ntp < 4; ntp++) {
                    mma16816(sacc[2 * ntp],     ql[ks], kf[ntp][0], kf[ntp][1]);
                    mma16816(sacc[2 * ntp + 1], ql[ks], kf[ntp][2], kf[ntp][3]);
                }
            }

            const bool maybe_mask = (kt * 64 + 63 > row0);
            float mx0 = -1e30f, mx1 = -1e30f;
            #pragma unroll
            for (int nt = 0; nt < 8; nt++) {
                #pragma unroll
                for (int r = 0; r < 4; r++) sacc[nt][r] *= scale;
                if (maybe_mask) {
                    int colb = kt * 64 + nt * 8 + 2 * t4;
                    if (colb > r_g)      sacc[nt][0] = NEG_BIG;
                    if (colb + 1 > r_g)  sacc[nt][1] = NEG_BIG;
                    if (colb > r_g8)     sacc[nt][2] = NEG_BIG;
                    if (colb + 1 > r_g8) sacc[nt][3] = NEG_BIG;
                }
                mx0 = fmaxf(mx0, fmaxf(sacc[nt][0], sacc[nt][1]));
                mx1 = fmaxf(mx1, fmaxf(sacc[nt][2], sacc[nt][3]));
            }
            mx0 = fmaxf(mx0, __shfl_xor_sync(0xffffffffu, mx0, 1));
            mx0 = fmaxf(mx0, __shfl_xor_sync(0xffffffffu, mx0, 2));
            mx1 = fmaxf(mx1, __shfl_xor_sync(0xffffffffu, mx1, 1));
            mx1 = fmaxf(mx1, __shfl_xor_sync(0xffffffffu, mx1, 2));

            float mn0 = fmaxf(m0, mx0), mn1 = fmaxf(m1, mx1);
            float corr0 = __expf(m0 - mn0), corr1 = __expf(m1 - mn1);

            uint32_t ph[8][2];
            float rs0 = 0.f, rs1 = 0.f;
            #pragma unroll
            for (int nt = 0; nt < 8; nt++) {
                float p00 = __expf(sacc[nt][0] - mn0);
                float p01 = __expf(sacc[nt][1] - mn0);
                float p10 = __expf(sacc[nt][2] - mn1);
                float p11 = __expf(sacc[nt][3] - mn1);
                rs0 += p00 + p01;
                rs1 += p10 + p11;
                ph[nt][0] = pack_f16x2(p00, p01);
                ph[nt][1] = pack_f16x2(p10, p11);
            }
            rs0 += __shfl_xor_sync(0xffffffffu, rs0, 1);
            rs0 += __shfl_xor_sync(0xffffffffu, rs0, 2);
            rs1 += __shfl_xor_sync(0xffffffffu, rs1, 1);
            rs1 += __shfl_xor_sync(0xffffffffu, rs1, 2);

            l0 = l0 * corr0 + rs0;
            l1 = l1 * corr1 + rs1;
            m0 = mn0; m1 = mn1;
            #pragma unroll
            for (int nt = 0; nt < 8; nt++) {
                oacc[nt][0] *= corr0; oacc[nt][1] *= corr0;
                oacc[nt][2] *= corr1; oacc[nt][3] *= corr1;
            }

            #pragma unroll
            for (int ks = 0; ks < 4; ks++) {
                uint32_t pah[4] = { ph[2 * ks][0], ph[2 * ks][1], ph[2 * ks + 1][0], ph[2 * ks + 1][1] };
                uint32_t vfh[4][4];
                #pragma unroll
                for (int ntp = 0; ntp < 4; ntp++) {
                    uint32_t bd = kvb + 2u * (uint32_t)(VH_OFF + (ntp * 16 + brow_l) * FPITCH + ks * 16 + bcol_l);
                    LDM4(vfh[ntp][0], vfh[ntp][1], vfh[ntp][2], vfh[ntp][3], bd);
                }
                #pragma unroll
                for (int ntp = 0; ntp < 4; ntp++) {
                    mma16816(oacc[2 * ntp],     pah, vfh[ntp][0], vfh[ntp][1]);
                    mma16816(oacc[2 * ntp + 1], pah, vfh[ntp][2], vfh[ntp][3]);
                }
            }
            __syncthreads();
        }

        // ---- epilogue: only hi output needed (x1 Wo GEMM ignores lo) ----
        float inv0 = 1.0f / l0, inv1 = 1.0f / l1;
        uint32_t* oHi = (uint32_t*)outHi;
        #pragma unroll
        for (int nt = 0; nt < 8; nt++) {
            float o00 = oacc[nt][0] * inv0, o01 = oacc[nt][1] * inv0;
            float o10 = oacc[nt][2] * inv1, o11 = oacc[nt][3] * inv1;
            size_t row = (size_t)b * SEQ + qt * 128 + wid * 16 + g;
            int col = h * 64 + nt * 8 + 2 * t4;
            oHi[(row * 2048 + col) >> 1] = pack_f16x2(o00, o01);
            oHi[((row + 8) * 2048 + col) >> 1] = pack_f16x2(o10, o11);
        }
        (void)outLo;
    }
}

// ---------------- launcher ----------------
extern "C" void kernel_launch(void* const* d_in, const int* in_sizes, int n_in,
                              void* d_out, int out_size)
{
    const float* hidden = (const float*)d_in[0];
    const float* Wq = (const float*)d_in[2];
    const float* Wk = (const float*)d_in[3];
    const float* Wv = (const float*)d_in[4];
    const float* Wo = (const float*)d_in[5];
    float* out = (float*)d_out;

    float* qkv_ptr;
    cudaGetSymbolAddress((void**)&qkv_ptr, g_qkv);

    __half *aHi, *aLo, *bQKV, *bO;
    __half *qH, *qL, *kH, *vtH;
    cudaGetSymbolAddress((void**)&aHi, gA_hi);
    cudaGetSymbolAddress((void**)&aLo, gA_lo);
    cudaGetSymbolAddress((void**)&bQKV, gBqkv);
    cudaGetSymbolAddress((void**)&bO, gBo);
    cudaGetSymbolAddress((void**)&qH, gQhi);
    cudaGetSymbolAddress((void**)&qL, gQlo);
    cudaGetSymbolAddress((void**)&kH, gKhi);
    cudaGetSymbolAddress((void**)&vtH, gVThi);

    cudaFuncSetAttribute(gemm_fp16x2_kernel, cudaFuncAttributeMaxDynamicSharedMemorySize, GEMM_SMEM);
    cudaFuncSetAttribute(gemm_fp16x1_kernel, cudaFuncAttributeMaxDynamicSharedMemorySize, GEMM1_SMEM);
    cudaFuncSetAttribute(flash_mma_kernel, cudaFuncAttributeMaxDynamicSharedMemorySize, FLASH_SMEM);

    // 1) fused input prep
    input_prep_kernel<<<IN_TOTAL_BLKS, 256>>>(hidden, Wq, Wk, Wv, Wo, aHi, aLo, bQKV, bO);

    // 2) fused QKV projection (hi+lo A — precision-critical)
    gemm_fp16x2_kernel<<<dim3(NQKV / 128, MROWS / 64), 128, GEMM_SMEM>>>(aHi, aLo, bQKV, qkv_ptr, NQKV);

    // 3) fused prep (rope Q, rope K, V transpose hi-only)
    prep_kernel<<<PREP_TOTAL_BLKS, 256>>>(qkv_ptr, qH, qL, kH, vtH);

    // 4) attention (writes fp16 hi output into aHi)
    {
        dim3 g(NQT / 2, BATCH * HQ);
        flash_mma_kernel<<<g, 256, FLASH_SMEM>>>(qH, qL, kH, vtH, aHi, aLo);
    }

    // 5) output projection (single-A fp16 — error within budget)
    gemm_fp16x1_kernel<<<dim3(2048 / 128, MROWS / 64), 128, GEMM1_SMEM>>>(aHi, bO, out, 2048);
}

// round 16
// speedup vs baseline: 1.2455x; 1.0362x over previous
#include <cuda_runtime.h>
#include <cuda_fp16.h>
#include <math.h>
#include <stdint.h>

// ---------------- problem constants ----------------
#define BATCH 2
#define SEQ 1024
#define HIDDEN 2048
#define HQ 32
#define HKV 8
#define HD 64
#define MROWS (BATCH * SEQ)     // 2048
#define KDIM HIDDEN             // 2048
#define NQKV 3072
#define NEG_BIG (-1e9f)

// ---------------- scratch ----------------
__device__ float g_qkv[MROWS * NQKV];

__device__ __half gA_hi[MROWS * KDIM];
__device__ __half gA_lo[MROWS * KDIM];
__device__ __half gBqkv[NQKV * KDIM];
__device__ __half gBo[2048 * KDIM];

__device__ __half gQhi[MROWS * HQ * HD];
__device__ __half gKhi[MROWS * HKV * HD];
__device__ __half gVThi[BATCH * HKV * HD * SEQ];

// ---------------- helpers ----------------
__device__ __forceinline__ uint32_t smem_to_u32(const void* p) {
    uint32_t a;
    asm("{ .reg .u64 t; cvta.to.shared.u64 t, %1; cvt.u32.u64 %0, t; }" : "=r"(a) : "l"(p));
    return a;
}
#define LDM4(r0, r1, r2, r3, addr) \
    asm volatile("ldmatrix.sync.aligned.m8n8.x4.shared.b16 {%0,%1,%2,%3}, [%4];" \
        : "=r"(r0), "=r"(r1), "=r"(r2), "=r"(r3) : "r"(addr))

__device__ __forceinline__ void mma16816(float* d, const uint32_t* a, uint32_t b0, uint32_t b1) {
    asm volatile("mma.sync.aligned.m16n8k16.row.col.f32.f16.f16.f32 "
        "{%0,%1,%2,%3}, {%4,%5,%6,%7}, {%8,%9}, {%0,%1,%2,%3};"
        : "+f"(d[0]), "+f"(d[1]), "+f"(d[2]), "+f"(d[3])
        : "r"(a[0]), "r"(a[1]), "r"(a[2]), "r"(a[3]), "r"(b0), "r"(b1));
}
__device__ __forceinline__ uint32_t pack_f16x2(float lo, float hi) {
    uint32_t d;
    asm("cvt.rn.f16x2.f32 %0, %1, %2;" : "=r"(d) : "f"(hi), "f"(lo));
    return d;
}

// ---------------- fp16x2 GEMM (hi+lo A): 64x128 tile, BK=32, 3 stages, occ 3 ----------------
#define BK 32
#define PITCH 40
#define A_ELEMS (64 * PITCH)
#define B_ELEMS (128 * PITCH)
#define STAGE_ELEMS (2 * A_ELEMS + B_ELEMS)
#define NSTAGE 3
#define GEMM_SMEM (NSTAGE * STAGE_ELEMS * 2)        // 61440 bytes
#define NCHUNK (KDIM / BK)

__device__ __forceinline__ void issue_stage(
    uint32_t sb, int stage,
    const __half* __restrict__ Ahi, const __half* __restrict__ Alo,
    const __half* __restrict__ B,
    int m0, int n0, int k0, int tid)
{
    #pragma unroll
    for (int t = 0; t < 8; t++) {
        int idx = tid + t * 128;
        int ch = idx & 3;
        const __half* src;
        uint32_t dstoff;
        if (idx < 512) {
            int tl = idx >> 8;
            int row = (idx >> 2) & 63;
            src = (tl ? Alo : Ahi) + (size_t)(m0 + row) * KDIM + k0 + ch * 8;
            dstoff = (uint32_t)(tl * A_ELEMS + row * PITCH + ch * 8);
        } else {
            int row = (idx >> 2) & 127;
            src = B + (size_t)(n0 + row) * KDIM + k0 + ch * 8;
            dstoff = (uint32_t)(2 * A_ELEMS + row * PITCH + ch * 8);
        }
        uint32_t dst = sb + 2u * ((uint32_t)stage * STAGE_ELEMS + dstoff);
        asm volatile("cp.async.cg.shared.global [%0], [%1], 16;" :: "r"(dst), "l"(src));
    }
    asm volatile("cp.async.commit_group;");
}

__global__ __launch_bounds__(128, 3) void gemm_fp16x2_kernel(
    const __half* __restrict__ Ahi, const __half* __restrict__ Alo,
    const __half* __restrict__ B,
    float* __restrict__ C, int N)
{
    extern __shared__ char smem[];
    const uint32_t sb = smem_to_u32(smem);
    const int tid = threadIdx.x;
    const int wid = tid >> 5;
    const int lid = tid & 31;
    const int g = lid >> 2;
    const int t4 = lid & 3;
    const int n0 = blockIdx.x * 128;
    const int m0 = blockIdx.y * 64;

    const int arow_l = (lid & 7) + ((lid >> 3) & 1) * 8;
    const int acol_l = (lid >> 4) * 8;
    const int brow_l = (lid & 7) + (lid >> 4) * 8;
    const int bcol_l = ((lid >> 3) & 1) * 8;

    float acc[4][4][4];
    #pragma unroll
    for (int i = 0; i < 4; i++)
        #pragma unroll
        for (int j = 0; j < 4; j++)
            #pragma unroll
            for (int r = 0; r < 4; r++) acc[i][j][r] = 0.f;

    issue_stage(sb, 0, Ahi, Alo, B, m0, n0, 0, tid);
    issue_stage(sb, 1, Ahi, Alo, B, m0, n0, BK, tid);

    int p = 0;
    for (int i = 0; i < NCHUNK; i++) {
        if (i < NCHUNK - 1) {
            asm volatile("cp.async.wait_group 1;" ::: "memory");
        } else {
            asm volatile("cp.async.wait_group 0;" ::: "memory");
        }
        __syncthreads();

        if (i + 2 < NCHUNK) {
            int st = p + 2; if (st >= NSTAGE) st -= NSTAGE;
            issue_stage(sb, st, Ahi, Alo, B, m0, n0, (i + 2) * BK, tid);
        }

        const uint32_t base = sb + 2u * (uint32_t)(p * STAGE_ELEMS);
        #pragma unroll
        for (int ks = 0; ks < 2; ks++) {
            const int kb = ks * 16;
            uint32_t ah[4][4], al[4][4], bb[4][2];
            #pragma unroll
            for (int mt = 0; mt < 4; mt++) {
                uint32_t ad = base + 2u * (uint32_t)((mt * 16 + arow_l) * PITCH + kb + acol_l);
                LDM4(ah[mt][0], ah[mt][1], ah[mt][2], ah[mt][3], ad);
                LDM4(al[mt][0], al[mt][1], al[mt][2], al[mt][3], ad + 2u * A_ELEMS);
            }
            #pragma unroll
            for (int ntp = 0; ntp < 2; ntp++) {
                uint32_t bd = base + 2u * (uint32_t)(2 * A_ELEMS + (wid * 32 + ntp * 16 + brow_l) * PITCH + kb + bcol_l);
                uint32_t r0, r1, r2, r3;
                LDM4(r0, r1, r2, r3, bd);
                bb[2 * ntp][0] = r0; bb[2 * ntp][1] = r1;
                bb[2 * ntp + 1][0] = r2; bb[2 * ntp + 1][1] = r3;
            }
            #pragma unroll
            for (int mt = 0; mt < 4; mt++)
                #pragma unroll
                for (int nt = 0; nt < 4; nt++)
                    mma16816(acc[mt][nt], ah[mt], bb[nt][0], bb[nt][1]);
            #pragma unroll
            for (int mt = 0; mt < 4; mt++)
                #pragma unroll
                for (int nt = 0; nt < 4; nt++)
                    mma16816(acc[mt][nt], al[mt], bb[nt][0], bb[nt][1]);
        }
        if (++p == NSTAGE) p = 0;
    }

    #pragma unroll
    for (int mt = 0; mt < 4; mt++) {
        int row = m0 + mt * 16 + g;
        #pragma unroll
        for (int nt = 0; nt < 4; nt++) {
            int col = n0 + wid * 32 + nt * 8 + 2 * t4;
            *(float2*)&C[(size_t)row * N + col] = make_float2(acc[mt][nt][0], acc[mt][nt][1]);
            *(float2*)&C[(size_t)(row + 8) * N + col] = make_float2(acc[mt][nt][2], acc[mt][nt][3]);
        }
    }
}

// ---------------- fp16x1 GEMM (single A): 64x128 tile, BK=32, 3 stages, occ 4 ----------------
#define STAGE1_ELEMS (A_ELEMS + B_ELEMS)
#define GEMM1_SMEM (NSTAGE * STAGE1_ELEMS * 2)      // 46080 bytes

__device__ __forceinline__ void issue_stage_x1(
    uint32_t sb, int stage,
    const __half* __restrict__ A, const __half* __restrict__ B,
    int m0, int n0, int k0, int tid)
{
    #pragma unroll
    for (int t = 0; t < 6; t++) {
        int idx = tid + t * 128;
        int ch = idx & 3;
        const __half* src;
        uint32_t dstoff;
        if (idx < 256) {
            int row = (idx >> 2) & 63;
            src = A + (size_t)(m0 + row) * KDIM + k0 + ch * 8;
            dstoff = (uint32_t)(row * PITCH + ch * 8);
        } else {
            int row = ((idx - 256) >> 2) & 127;
            src = B + (size_t)(n0 + row) * KDIM + k0 + ch * 8;
            dstoff = (uint32_t)(A_ELEMS + row * PITCH + ch * 8);
        }
        uint32_t dst = sb + 2u * ((uint32_t)stage * STAGE1_ELEMS + dstoff);
        asm volatile("cp.async.cg.shared.global [%0], [%1], 16;" :: "r"(dst), "l"(src));
    }
    asm volatile("cp.async.commit_group;");
}

__global__ __launch_bounds__(128, 4) void gemm_fp16x1_kernel(
    const __half* __restrict__ A, const __half* __restrict__ B,
    float* __restrict__ C, int N)
{
    extern __shared__ char smem[];
    const uint32_t sb = smem_to_u32(smem);
    const int tid = threadIdx.x;
    const int wid = tid >> 5;
    const int lid = tid & 31;
    const int g = lid >> 2;
    const int t4 = lid & 3;
    const int n0 = blockIdx.x * 128;
    const int m0 = blockIdx.y * 64;

    const int arow_l = (lid & 7) + ((lid >> 3) & 1) * 8;
    const int acol_l = (lid >> 4) * 8;
    const int brow_l = (lid & 7) + (lid >> 4) * 8;
    const int bcol_l = ((lid >> 3) & 1) * 8;

    float acc[4][4][4];
    #pragma unroll
    for (int i = 0; i < 4; i++)
        #pragma unroll
        for (int j = 0; j < 4; j++)
            #pragma unroll
            for (int r = 0; r < 4; r++) acc[i][j][r] = 0.f;

    issue_stage_x1(sb, 0, A, B, m0, n0, 0, tid);
    issue_stage_x1(sb, 1, A, B, m0, n0, BK, tid);

    int p = 0;
    for (int i = 0; i < NCHUNK; i++) {
        if (i < NCHUNK - 1) {
            asm volatile("cp.async.wait_group 1;" ::: "memory");
        } else {
            asm volatile("cp.async.wait_group 0;" ::: "memory");
        }
        __syncthreads();

        if (i + 2 < NCHUNK) {
            int st = p + 2; if (st >= NSTAGE) st -= NSTAGE;
            issue_stage_x1(sb, st, A, B, m0, n0, (i + 2) * BK, tid);
        }

        const uint32_t base = sb + 2u * (uint32_t)(p * STAGE1_ELEMS);
        #pragma unroll
        for (int ks = 0; ks < 2; ks++) {
            const int kb = ks * 16;
            uint32_t ah[4][4], bb[4][2];
            #pragma unroll
            for (int mt = 0; mt < 4; mt++) {
                uint32_t ad = base + 2u * (uint32_t)((mt * 16 + arow_l) * PITCH + kb + acol_l);
                LDM4(ah[mt][0], ah[mt][1], ah[mt][2], ah[mt][3], ad);
            }
            #pragma unroll
            for (int ntp = 0; ntp < 2; ntp++) {
                uint32_t bd = base + 2u * (uint32_t)(A_ELEMS + (wid * 32 + ntp * 16 + brow_l) * PITCH + kb + bcol_l);
                uint32_t r0, r1, r2, r3;
                LDM4(r0, r1, r2, r3, bd);
                bb[2 * ntp][0] = r0; bb[2 * ntp][1] = r1;
                bb[2 * ntp + 1][0] = r2; bb[2 * ntp + 1][1] = r3;
            }
            #pragma unroll
            for (int mt = 0; mt < 4; mt++)
                #pragma unroll
                for (int nt = 0; nt < 4; nt++)
                    mma16816(acc[mt][nt], ah[mt], bb[nt][0], bb[nt][1]);
        }
        if (++p == NSTAGE) p = 0;
    }

    #pragma unroll
    for (int mt = 0; mt < 4; mt++) {
        int row = m0 + mt * 16 + g;
        #pragma unroll
        for (int nt = 0; nt < 4; nt++) {
            int col = n0 + wid * 32 + nt * 8 + 2 * t4;
            *(float2*)&C[(size_t)row * N + col] = make_float2(acc[mt][nt][0], acc[mt][nt][1]);
            *(float2*)&C[(size_t)(row + 8) * N + col] = make_float2(acc[mt][nt][2], acc[mt][nt][3]);
        }
    }
}

// ---------------- fused input prep ----------------
#define ISPLIT_BLKS 4096
#define WT_BLKS (160 * 64)
#define IN_TOTAL_BLKS (ISPLIT_BLKS + WT_BLKS)

__global__ void input_prep_kernel(const float* __restrict__ hidden,
                                  const float* __restrict__ Wq, const float* __restrict__ Wk,
                                  const float* __restrict__ Wv, const float* __restrict__ Wo,
                                  __half* __restrict__ aHi, __half* __restrict__ aLo,
                                  __half* __restrict__ bQKV, __half* __restrict__ bO)
{
    const int blk = blockIdx.x;
    const int tid = threadIdx.x;

    if (blk < ISPLIT_BLKS) {
        int i = blk * 256 + tid;
        float4 v = ((const float4*)hidden)[i];
        __half h0 = __float2half_rn(v.x), h1 = __float2half_rn(v.y);
        __half h2 = __float2half_rn(v.z), h3 = __float2half_rn(v.w);
        uint2 hv, lv;
        hv.x = pack_f16x2(__half2float(h0), __half2float(h1));
        hv.y = pack_f16x2(__half2float(h2), __half2float(h3));
        lv.x = pack_f16x2(v.x - __half2float(h0), v.y - __half2float(h1));
        lv.y = pack_f16x2(v.z - __half2float(h2), v.w - __half2float(h3));
        ((uint2*)aHi)[i] = hv;
        ((uint2*)aLo)[i] = lv;
    } else {
        __shared__ float t[32][33];
        int local = blk - ISPLIT_BLKS;
        const int ntile = local % 160;
        const int k0 = (local / 160) * 32;
        const float* W;  __half* dst;  int N;  int n0;
        if (ntile < 64)      { W = Wq; dst = bQKV;                       N = 2048; n0 = ntile * 32; }
        else if (ntile < 80) { W = Wk; dst = bQKV + (size_t)2048 * KDIM; N = 512;  n0 = (ntile - 64) * 32; }
        else if (ntile < 96) { W = Wv; dst = bQKV + (size_t)2560 * KDIM; N = 512;  n0 = (ntile - 80) * 32; }
        else                 { W = Wo; dst = bO;                         N = 2048; n0 = (ntile - 96) * 32; }

        const int tx = tid & 31, ty = tid >> 5;
        #pragma unroll
        for (int i = 0; i < 32; i += 8)
            t[ty + i][tx] = W[(size_t)(k0 + ty + i) * N + n0 + tx];
        __syncthreads();
        #pragma unroll
        for (int i = 0; i < 32; i += 8) {
            float v = t[tx][ty + i];
            dst[(size_t)(n0 + ty + i) * KDIM + k0 + tx] = __float2half_rn(v);
        }
    }
}

// ---------------- fused prep: rope(Q) | rope(K) | V-transpose (all hi-only) ----------------
#define PREP_ROPEQ_BLKS 8192
#define PREP_ROPEK_BLKS 2048
#define PREP_VT_BLKS 1024
#define PREP_TOTAL_BLKS (PREP_ROPEQ_BLKS + PREP_ROPEK_BLKS + PREP_VT_BLKS)

__device__ __forceinline__ void rope_body(const float* __restrict__ qkv, int colOff,
                                          __half* __restrict__ hi, int heads, int idx)
{
    int dpair = idx & 31;
    int t = idx >> 5;
    int h = t % heads;  t /= heads;
    int s = t % SEQ;
    int b = t / SEQ;

    float inv = powf(10000.0f, -(float)(2 * dpair) / (float)HD);
    float ang = (float)s * inv;
    float sn, cs;
    sincosf(ang, &sn, &cs);

    size_t src = ((size_t)b * SEQ + s) * NQKV + colOff + h * HD + dpair;
    float x1 = qkv[src];
    float x2 = qkv[src + HD / 2];
    float y1 = x1 * cs - x2 * sn;
    float y2 = x2 * cs + x1 * sn;

    size_t base = (((size_t)b * SEQ + s) * heads + h) * HD + dpair;
    hi[base] = __float2half_rn(y1);
    hi[base + HD / 2] = __float2half_rn(y2);
}

__global__ void prep_kernel(const float* __restrict__ qkv,
                            __half* __restrict__ qH,
                            __half* __restrict__ kH,
                            __half* __restrict__ vtH)
{
    const int blk = blockIdx.x;
    const int tid = threadIdx.x;

    if (blk < PREP_ROPEQ_BLKS) {
        rope_body(qkv, 0, qH, HQ, blk * 256 + tid);
    } else if (blk < PREP_ROPEQ_BLKS + PREP_ROPEK_BLKS) {
        rope_body(qkv, 2048, kH, HKV, (blk - PREP_ROPEQ_BLKS) * 256 + tid);
    } else {
        __shared__ float t[32][33];
        int local = blk - PREP_ROPEQ_BLKS - PREP_ROPEK_BLKS;
        const int s0 = (local & 31) * 32;
        const int d0 = ((local >> 5) & 1) * 32;
        const int bh = local >> 6;
        const int b = bh >> 3;
        const int h = bh & 7;
        const int tx = tid & 31, ty = tid >> 5;
        #pragma unroll
        for (int i = 0; i < 32; i += 8)
            t[ty + i][tx] = qkv[((size_t)b * SEQ + s0 + ty + i) * NQKV + 2560 + h * HD + d0 + tx];
        __syncthreads();
        #pragma unroll
        for (int i = 0; i < 32; i += 8) {
            float x = t[tx][ty + i];
            size_t o = (((size_t)b * HKV + h) * HD + d0 + ty + i) * SEQ + s0 + tx;
            vtH[o] = __float2half_rn(x);
        }
    }
}

// ---------------- flash: Q single, K single, V single; 2-tile KV stages ----------------
#define FPITCH 72
#define KH_OFF 0
#define VH_OFF (64 * FPITCH)
#define KV_STAGE_ELEMS (128 * FPITCH)
#define FLASH_SMEM (2 * KV_STAGE_ELEMS * 2)        // 36864 bytes
#define NQT (SEQ / 128)

__device__ __forceinline__ void flash_issue_kv(
    uint32_t sb, int stage,
    const __half* __restrict__ khi, const __half* __restrict__ vthi,
    int b, int hkv, int kt, int tid)
{
    #pragma unroll
    for (int it = 0; it < 4; it++) {
        int idx = tid + it * 256;
        int tile = idx >> 9;
        int r = (idx >> 3) & 63;
        int ch = idx & 7;
        const __half* src;
        int dstoff;
        if (tile == 0) { src = &khi[(((size_t)b * SEQ + kt * 64 + r) * HKV + hkv) * HD + ch * 8]; dstoff = KH_OFF; }
        else { src = &vthi[(((size_t)b * HKV + hkv) * HD + r) * SEQ + kt * 64 + ch * 8]; dstoff = VH_OFF; }
        uint32_t dst = sb + 2u * (uint32_t)(stage * KV_STAGE_ELEMS + dstoff + r * FPITCH + ch * 8);
        asm volatile("cp.async.cg.shared.global [%0], [%1], 16;" :: "r"(dst), "l"(src));
    }
    asm volatile("cp.async.commit_group;");
}

__global__ __launch_bounds__(256, 2) void flash_mma_kernel(
    const __half* __restrict__ qhi,
    const __half* __restrict__ khi, const __half* __restrict__ vthi,
    __half* __restrict__ outHi)
{
    extern __shared__ char smem[];
    const uint32_t sb = smem_to_u32(smem);
    __half* sm = (__half*)smem;

    const int tid = threadIdx.x;
    const int wid = tid >> 5;
    const int lid = tid & 31;
    const int g = lid >> 2;
    const int t4 = lid & 3;
    const int pairIdx = blockIdx.x;
    const int bh = blockIdx.y;
    const int b = bh >> 5;
    const int h = bh & 31;
    const int hkv = h >> 2;

    const int arow_l = (lid & 7) + ((lid >> 3) & 1) * 8;
    const int acol_l = (lid >> 4) * 8;
    const int brow_l = (lid & 7) + (lid >> 4) * 8;
    const int bcol_l = ((lid >> 3) & 1) * 8;

    const float scale = 0.125f;

    #pragma unroll
    for (int half = 0; half < 2; half++) {
        const int qt = half ? (NQT - 1 - pairIdx) : pairIdx;

        // ---- stage Q (128 x 64 hi only; overlays stage-0 KV region exactly) ----
        __syncthreads();
        #pragma unroll
        for (int it = 0; it < 4; it++) {
            int idx = tid + it * 256;
            int row = idx >> 3;
            int ch = idx & 7;
            size_t goff = (((size_t)b * SEQ + qt * 128 + row) * HQ + h) * HD + ch * 8;
            *(uint4*)&sm[row * FPITCH + ch * 8] = *(const uint4*)&qhi[goff];
        }
        __syncthreads();

        uint32_t qh[4][4];
        #pragma unroll
        for (int ks = 0; ks < 4; ks++) {
            uint32_t ad = sb + 2u * (uint32_t)((wid * 16 + arow_l) * FPITCH + ks * 16 + acol_l);
            LDM4(qh[ks][0], qh[ks][1], qh[ks][2], qh[ks][3], ad);
        }
        __syncthreads();

        float m0 = -1e30f, m1 = -1e30f, l0 = 0.f, l1 = 0.f;
        float oacc[8][4];
        #pragma unroll
        for (int nt = 0; nt < 8; nt++)
            #pragma unroll
            for (int r = 0; r < 4; r++) oacc[nt][r] = 0.f;

        const int row0 = qt * 128 + wid * 16;
        const int r_g = row0 + g;
        const int r_g8 = r_g + 8;
        const int nkt = 2 * qt + 2;

        flash_issue_kv(sb, 0, khi, vthi, b, hkv, 0, tid);

        for (int kt = 0; kt < nkt; kt++) {
            const int stg = kt & 1;
            if (kt + 1 < nkt) {
                flash_issue_kv(sb, 1 - stg, khi, vthi, b, hkv, kt + 1, tid);
                asm volatile("cp.async.wait_group 1;" ::: "memory");
            } else {
                asm volatile("cp.async.wait_group 0;" ::: "memory");
            }
            __syncthreads();

            const uint32_t kvb = sb + 2u * (uint32_t)(stg * KV_STAGE_ELEMS);

            float sacc[8][4];
            #pragma unroll
            for (int nt = 0; nt < 8; nt++)
                #pragma unroll
                for (int r = 0; r < 4; r++) sacc[nt][r] = 0.f;

            #pragma unroll
            for (int ks = 0; ks < 4; ks++) {
                uint32_t kf[4][4];
                #pragma unroll
                for (int ntp = 0; ntp < 4; ntp++) {
                    uint32_t bd = kvb + 2u * (uint32_t)(KH_OFF + (ntp * 16 + brow_l) * FPITCH + ks * 16 + bcol_l);
                    LDM4(kf[ntp][0], kf[ntp][1], kf[ntp][2], kf[ntp][3], bd);
                }
                #pragma unroll
                for (int ntp = 0; ntp < 4; ntp++) {
                    mma16816(sacc[2 * ntp],     qh[ks], kf[ntp][0], kf[ntp][1]);
                    mma16816(sacc[2 * ntp + 1], qh[ks], kf[ntp][2], kf[ntp][3]);
                }
            }

            const bool maybe_mask = (kt * 64 + 63 > row0);
            float mx0 = -1e30f, mx1 = -1e30f;
            #pragma unroll
            for (int nt = 0; nt < 8; nt++) {
                #pragma unroll
                for (int r = 0; r < 4; r++) sacc[nt][r] *= scale;
                if (maybe_mask) {
                    int colb = kt * 64 + nt * 8 + 2 * t4;
                    if (colb > r_g)      sacc[nt][0] = NEG_BIG;
                    if (colb + 1 > r_g)  sacc[nt][1] = NEG_BIG;
                    if (colb > r_g8)     sacc[nt][2] = NEG_BIG;
                    if (colb + 1 > r_g8) sacc[nt][3] = NEG_BIG;
                }
                mx0 = fmaxf(mx0, fmaxf(sacc[nt][0], sacc[nt][1]));
                mx1 = fmaxf(mx1, fmaxf(sacc[nt][2], sacc[nt][3]));
            }
            mx0 = fmaxf(mx0, __shfl_xor_sync(0xffffffffu, mx0, 1));
            mx0 = fmaxf(mx0, __shfl_xor_sync(0xffffffffu, mx0, 2));
            mx1 = fmaxf(mx1, __shfl_xor_sync(0xffffffffu, mx1, 1));
            mx1 = fmaxf(mx1, __shfl_xor_sync(0xffffffffu, mx1, 2));

            float mn0 = fmaxf(m0, mx0), mn1 = fmaxf(m1, mx1);
            float corr0 = __expf(m0 - mn0), corr1 = __expf(m1 - mn1);

            uint32_t ph[8][2];
            float rs0 = 0.f, rs1 = 0.f;
            #pragma unroll
            for (int nt = 0; nt < 8; nt++) {
                float p00 = __expf(sacc[nt][0] - mn0);
                float p01 = __expf(sacc[nt][1] - mn0);
                float p10 = __expf(sacc[nt][2] - mn1);
                float p11 = __expf(sacc[nt][3] - mn1);
                rs0 += p00 + p01;
                rs1 += p10 + p11;
                ph[nt][0] = pack_f16x2(p00, p01);
                ph[nt][1] = pack_f16x2(p10, p11);
            }
            rs0 += __shfl_xor_sync(0xffffffffu, rs0, 1);
            rs0 += __shfl_xor_sync(0xffffffffu, rs0, 2);
            rs1 += __shfl_xor_sync(0xffffffffu, rs1, 1);
            rs1 += __shfl_xor_sync(0xffffffffu, rs1, 2);

            l0 = l0 * corr0 + rs0;
            l1 = l1 * corr1 + rs1;
            m0 = mn0; m1 = mn1;
            #pragma unroll
            for (int nt = 0; nt < 8; nt++) {
                oacc[nt][0] *= corr0; oacc[nt][1] *= corr0;
                oacc[nt][2] *= corr1; oacc[nt][3] *= corr1;
            }

            #pragma unroll
            for (int ks = 0; ks < 4; ks++) {
                uint32_t pah[4] = { ph[2 * ks][0], ph[2 * ks][1], ph[2 * ks + 1][0], ph[2 * ks + 1][1] };
                uint32_t vfh[4][4];
                #pragma unroll
                for (int ntp = 0; ntp < 4; ntp++) {
                    uint32_t bd = kvb + 2u * (uint32_t)(VH_OFF + (ntp * 16 + brow_l) * FPITCH + ks * 16 + bcol_l);
                    LDM4(vfh[ntp][0], vfh[ntp][1], vfh[ntp][2], vfh[ntp][3], bd);
                }
                #pragma unroll
                for (int ntp = 0; ntp < 4; ntp++) {
                    mma16816(oacc[2 * ntp],     pah, vfh[ntp][0], vfh[ntp][1]);
                    mma16816(oacc[2 * ntp + 1], pah, vfh[ntp][2], vfh[ntp][3]);
                }
            }
            __syncthreads();
        }

        // ---- epilogue: fp16 hi output ----
        float inv0 = 1.0f / l0, inv1 = 1.0f / l1;
        uint32_t* oHi = (uint32_t*)outHi;
        #pragma unroll
        for (int nt = 0; nt < 8; nt++) {
            float o00 = oacc[nt][0] * inv0, o01 = oacc[nt][1] * inv0;
            float o10 = oacc[nt][2] * inv1, o11 = oacc[nt][3] * inv1;
            size_t row = (size_t)b * SEQ + qt * 128 + wid * 16 + g;
            int col = h * 64 + nt * 8 + 2 * t4;
            oHi[(row * 2048 + col) >> 1] = pack_f16x2(o00, o01);
            oHi[((row + 8) * 2048 + col) >> 1] = pack_f16x2(o10, o11);
        }
    }
}

// ---------------- launcher ----------------
extern "C" void kernel_launch(void* const* d_in, const int* in_sizes, int n_in,
                              void* d_out, int out_size)
{
    const float* hidden = (const float*)d_in[0];
    const float* Wq = (const float*)d_in[2];
    const float* Wk = (const float*)d_in[3];
    const float* Wv = (const float*)d_in[4];
    const float* Wo = (const float*)d_in[5];
    float* out = (float*)d_out;

    float* qkv_ptr;
    cudaGetSymbolAddress((void**)&qkv_ptr, g_qkv);

    __half *aHi, *aLo, *bQKV, *bO;
    __half *qH, *kH, *vtH;
    cudaGetSymbolAddress((void**)&aHi, gA_hi);
    cudaGetSymbolAddress((void**)&aLo, gA_lo);
    cudaGetSymbolAddress((void**)&bQKV, gBqkv);
    cudaGetSymbolAddress((void**)&bO, gBo);
    cudaGetSymbolAddress((void**)&qH, gQhi);
    cudaGetSymbolAddress((void**)&kH, gKhi);
    cudaGetSymbolAddress((void**)&vtH, gVThi);

    cudaFuncSetAttribute(gemm_fp16x2_kernel, cudaFuncAttributeMaxDynamicSharedMemorySize, GEMM_SMEM);
    cudaFuncSetAttribute(gemm_fp16x1_kernel, cudaFuncAttributeMaxDynamicSharedMemorySize, GEMM1_SMEM);
    cudaFuncSetAttribute(flash_mma_kernel, cudaFuncAttributeMaxDynamicSharedMemorySize, FLASH_SMEM);

    // 1) fused input prep
    input_prep_kernel<<<IN_TOTAL_BLKS, 256>>>(hidden, Wq, Wk, Wv, Wo, aHi, aLo, bQKV, bO);

    // 2) fused QKV projection (hi+lo A — precision-critical)
    gemm_fp16x2_kernel<<<dim3(NQKV / 128, MROWS / 64), 128, GEMM_SMEM>>>(aHi, aLo, bQKV, qkv_ptr, NQKV);

    // 3) fused prep (rope Q hi-only, rope K hi-only, V transpose hi-only)
    prep_kernel<<<PREP_TOTAL_BLKS, 256>>>(qkv_ptr, qH, kH, vtH);

    // 4) attention (all operands single fp16; writes fp16 output into aHi)
    {
        dim3 g(NQT / 2, BATCH * HQ);
        flash_mma_kernel<<<g, 256, FLASH_SMEM>>>(qH, kH, vtH, aHi);
    }

    // 5) output projection (single-A fp16)
    gemm_fp16x1_kernel<<<dim3(2048 / 128, MROWS / 64), 128, GEMM1_SMEM>>>(aHi, bO, out, 2048);
}

// round 17
// speedup vs baseline: 1.5686x; 1.2594x over previous
#include <cuda_runtime.h>
#include <cuda_fp16.h>
#include <math.h>
#include <stdint.h>

// ---------------- problem constants ----------------
#define BATCH 2
#define SEQ 1024
#define HIDDEN 2048
#define HQ 32
#define HKV 8
#define HD 64
#define MROWS (BATCH * SEQ)     // 2048
#define KDIM HIDDEN             // 2048
#define NQKV 3072
#define NEG_BIG (-1e9f)

// ---------------- scratch ----------------
__device__ float g_qkv[MROWS * NQKV];

__device__ __half gA_hi[MROWS * KDIM];
__device__ __half gBqkv[NQKV * KDIM];
__device__ __half gBo[2048 * KDIM];

__device__ __half gQhi[MROWS * HQ * HD];
__device__ __half gKhi[MROWS * HKV * HD];
__device__ __half gVThi[BATCH * HKV * HD * SEQ];

// ---------------- helpers ----------------
__device__ __forceinline__ uint32_t smem_to_u32(const void* p) {
    uint32_t a;
    asm("{ .reg .u64 t; cvta.to.shared.u64 t, %1; cvt.u32.u64 %0, t; }" : "=r"(a) : "l"(p));
    return a;
}
#define LDM4(r0, r1, r2, r3, addr) \
    asm volatile("ldmatrix.sync.aligned.m8n8.x4.shared.b16 {%0,%1,%2,%3}, [%4];" \
        : "=r"(r0), "=r"(r1), "=r"(r2), "=r"(r3) : "r"(addr))

__device__ __forceinline__ void mma16816(float* d, const uint32_t* a, uint32_t b0, uint32_t b1) {
    asm volatile("mma.sync.aligned.m16n8k16.row.col.f32.f16.f16.f32 "
        "{%0,%1,%2,%3}, {%4,%5,%6,%7}, {%8,%9}, {%0,%1,%2,%3};"
        : "+f"(d[0]), "+f"(d[1]), "+f"(d[2]), "+f"(d[3])
        : "r"(a[0]), "r"(a[1]), "r"(a[2]), "r"(a[3]), "r"(b0), "r"(b1));
}
__device__ __forceinline__ uint32_t pack_f16x2(float lo, float hi) {
    uint32_t d;
    asm("cvt.rn.f16x2.f32 %0, %1, %2;" : "=r"(d) : "f"(hi), "f"(lo));
    return d;
}

// ---------------- fp16x1 GEMM (single A): 64x128 tile, BK=32, 3 stages, occ 4 ----------------
#define BK 32
#define PITCH 40
#define A_ELEMS (64 * PITCH)
#define B_ELEMS (128 * PITCH)
#define NSTAGE 3
#define NCHUNK (KDIM / BK)
#define STAGE1_ELEMS (A_ELEMS + B_ELEMS)            // 7680 elems = 15360 B
#define GEMM1_SMEM (NSTAGE * STAGE1_ELEMS * 2)      // 46080 bytes

__device__ __forceinline__ void issue_stage_x1(
    uint32_t sb, int stage,
    const __half* __restrict__ A, const __half* __restrict__ B,
    int m0, int n0, int k0, int tid)
{
    #pragma unroll
    for (int t = 0; t < 6; t++) {
        int idx = tid + t * 128;            // 0..767
        int ch = idx & 3;
        const __half* src;
        uint32_t dstoff;
        if (idx < 256) {
            int row = (idx >> 2) & 63;
            src = A + (size_t)(m0 + row) * KDIM + k0 + ch * 8;
            dstoff = (uint32_t)(row * PITCH + ch * 8);
        } else {
            int row = ((idx - 256) >> 2) & 127;
            src = B + (size_t)(n0 + row) * KDIM + k0 + ch * 8;
            dstoff = (uint32_t)(A_ELEMS + row * PITCH + ch * 8);
        }
        uint32_t dst = sb + 2u * ((uint32_t)stage * STAGE1_ELEMS + dstoff);
        asm volatile("cp.async.cg.shared.global [%0], [%1], 16;" :: "r"(dst), "l"(src));
    }
    asm volatile("cp.async.commit_group;");
}

__global__ __launch_bounds__(128, 4) void gemm_fp16x1_kernel(
    const __half* __restrict__ A, const __half* __restrict__ B,
    float* __restrict__ C, int N)
{
    extern __shared__ char smem[];
    const uint32_t sb = smem_to_u32(smem);
    const int tid = threadIdx.x;
    const int wid = tid >> 5;
    const int lid = tid & 31;
    const int g = lid >> 2;
    const int t4 = lid & 3;
    const int n0 = blockIdx.x * 128;
    const int m0 = blockIdx.y * 64;

    const int arow_l = (lid & 7) + ((lid >> 3) & 1) * 8;
    const int acol_l = (lid >> 4) * 8;
    const int brow_l = (lid & 7) + (lid >> 4) * 8;
    const int bcol_l = ((lid >> 3) & 1) * 8;

    float acc[4][4][4];
    #pragma unroll
    for (int i = 0; i < 4; i++)
        #pragma unroll
        for (int j = 0; j < 4; j++)
            #pragma unroll
            for (int r = 0; r < 4; r++) acc[i][j][r] = 0.f;

    issue_stage_x1(sb, 0, A, B, m0, n0, 0, tid);
    issue_stage_x1(sb, 1, A, B, m0, n0, BK, tid);

    int p = 0;
    for (int i = 0; i < NCHUNK; i++) {
        if (i < NCHUNK - 1) {
            asm volatile("cp.async.wait_group 1;" ::: "memory");
        } else {
            asm volatile("cp.async.wait_group 0;" ::: "memory");
        }
        __syncthreads();

        if (i + 2 < NCHUNK) {
            int st = p + 2; if (st >= NSTAGE) st -= NSTAGE;
            issue_stage_x1(sb, st, A, B, m0, n0, (i + 2) * BK, tid);
        }

        const uint32_t base = sb + 2u * (uint32_t)(p * STAGE1_ELEMS);
        #pragma unroll
        for (int ks = 0; ks < 2; ks++) {
            const int kb = ks * 16;
            uint32_t ah[4][4], bb[4][2];
            #pragma unroll
            for (int mt = 0; mt < 4; mt++) {
                uint32_t ad = base + 2u * (uint32_t)((mt * 16 + arow_l) * PITCH + kb + acol_l);
                LDM4(ah[mt][0], ah[mt][1], ah[mt][2], ah[mt][3], ad);
            }
            #pragma unroll
            for (int ntp = 0; ntp < 2; ntp++) {
                uint32_t bd = base + 2u * (uint32_t)(A_ELEMS + (wid * 32 + ntp * 16 + brow_l) * PITCH + kb + bcol_l);
                uint32_t r0, r1, r2, r3;
                LDM4(r0, r1, r2, r3, bd);
                bb[2 * ntp][0] = r0; bb[2 * ntp][1] = r1;
                bb[2 * ntp + 1][0] = r2; bb[2 * ntp + 1][1] = r3;
            }
            #pragma unroll
            for (int mt = 0; mt < 4; mt++)
                #pragma unroll
                for (int nt = 0; nt < 4; nt++)
                    mma16816(acc[mt][nt], ah[mt], bb[nt][0], bb[nt][1]);
        }
        if (++p == NSTAGE) p = 0;
    }

    #pragma unroll
    for (int mt = 0; mt < 4; mt++) {
        int row = m0 + mt * 16 + g;
        #pragma unroll
        for (int nt = 0; nt < 4; nt++) {
            int col = n0 + wid * 32 + nt * 8 + 2 * t4;
            *(float2*)&C[(size_t)row * N + col] = make_float2(acc[mt][nt][0], acc[mt][nt][1]);
            *(float2*)&C[(size_t)(row + 8) * N + col] = make_float2(acc[mt][nt][2], acc[mt][nt][3]);
        }
    }
}

// ---------------- fused input prep (A hi-only + weight transposes) ----------------
#define ISPLIT_BLKS 4096
#define WT_BLKS (160 * 64)
#define IN_TOTAL_BLKS (ISPLIT_BLKS + WT_BLKS)

__global__ void input_prep_kernel(const float* __restrict__ hidden,
                                  const float* __restrict__ Wq, const float* __restrict__ Wk,
                                  const float* __restrict__ Wv, const float* __restrict__ Wo,
                                  __half* __restrict__ aHi,
                                  __half* __restrict__ bQKV, __half* __restrict__ bO)
{
    const int blk = blockIdx.x;
    const int tid = threadIdx.x;

    if (blk < ISPLIT_BLKS) {
        int i = blk * 256 + tid;
        float4 v = ((const float4*)hidden)[i];
        uint2 hv;
        hv.x = pack_f16x2(v.x, v.y);
        hv.y = pack_f16x2(v.z, v.w);
        ((uint2*)aHi)[i] = hv;
    } else {
        __shared__ float t[32][33];
        int local = blk - ISPLIT_BLKS;
        const int ntile = local % 160;
        const int k0 = (local / 160) * 32;
        const float* W;  __half* dst;  int N;  int n0;
        if (ntile < 64)      { W = Wq; dst = bQKV;                       N = 2048; n0 = ntile * 32; }
        else if (ntile < 80) { W = Wk; dst = bQKV + (size_t)2048 * KDIM; N = 512;  n0 = (ntile - 64) * 32; }
        else if (ntile < 96) { W = Wv; dst = bQKV + (size_t)2560 * KDIM; N = 512;  n0 = (ntile - 80) * 32; }
        else                 { W = Wo; dst = bO;                         N = 2048; n0 = (ntile - 96) * 32; }

        const int tx = tid & 31, ty = tid >> 5;
        #pragma unroll
        for (int i = 0; i < 32; i += 8)
            t[ty + i][tx] = W[(size_t)(k0 + ty + i) * N + n0 + tx];
        __syncthreads();
        #pragma unroll
        for (int i = 0; i < 32; i += 8) {
            float v = t[tx][ty + i];
            dst[(size_t)(n0 + ty + i) * KDIM + k0 + tx] = __float2half_rn(v);
        }
    }
}

// ---------------- fused prep: rope(Q) | rope(K) | V-transpose ----------------
#define PREP_ROPEQ_BLKS 8192
#define PREP_ROPEK_BLKS 2048
#define PREP_VT_BLKS 1024
#define PREP_TOTAL_BLKS (PREP_ROPEQ_BLKS + PREP_ROPEK_BLKS + PREP_VT_BLKS)

__device__ __forceinline__ void rope_body(const float* __restrict__ qkv, int colOff,
                                          __half* __restrict__ hi, int heads, int idx)
{
    int dpair = idx & 31;
    int t = idx >> 5;
    int h = t % heads;  t /= heads;
    int s = t % SEQ;
    int b = t / SEQ;

    float inv = powf(10000.0f, -(float)(2 * dpair) / (float)HD);
    float ang = (float)s * inv;
    float sn, cs;
    sincosf(ang, &sn, &cs);

    size_t src = ((size_t)b * SEQ + s) * NQKV + colOff + h * HD + dpair;
    float x1 = qkv[src];
    float x2 = qkv[src + HD / 2];
    float y1 = x1 * cs - x2 * sn;
    float y2 = x2 * cs + x1 * sn;

    size_t base = (((size_t)b * SEQ + s) * heads + h) * HD + dpair;
    hi[base] = __float2half_rn(y1);
    hi[base + HD / 2] = __float2half_rn(y2);
}

__global__ void prep_kernel(const float* __restrict__ qkv,
                            __half* __restrict__ qH,
                            __half* __restrict__ kH,
                            __half* __restrict__ vtH)
{
    const int blk = blockIdx.x;
    const int tid = threadIdx.x;

    if (blk < PREP_ROPEQ_BLKS) {
        rope_body(qkv, 0, qH, HQ, blk * 256 + tid);
    } else if (blk < PREP_ROPEQ_BLKS + PREP_ROPEK_BLKS) {
        rope_body(qkv, 2048, kH, HKV, (blk - PREP_ROPEQ_BLKS) * 256 + tid);
    } else {
        __shared__ float t[32][33];
        int local = blk - PREP_ROPEQ_BLKS - PREP_ROPEK_BLKS;
        const int s0 = (local & 31) * 32;
        const int d0 = ((local >> 5) & 1) * 32;
        const int bh = local >> 6;
        const int b = bh >> 3;
        const int h = bh & 7;
        const int tx = tid & 31, ty = tid >> 5;
        #pragma unroll
        for (int i = 0; i < 32; i += 8)
            t[ty + i][tx] = qkv[((size_t)b * SEQ + s0 + ty + i) * NQKV + 2560 + h * HD + d0 + tx];
        __syncthreads();
        #pragma unroll
        for (int i = 0; i < 32; i += 8) {
            float x = t[tx][ty + i];
            size_t o = (((size_t)b * HKV + h) * HD + d0 + ty + i) * SEQ + s0 + tx;
            vtH[o] = __float2half_rn(x);
        }
    }
}

// ---------------- flash: Q/K/V single fp16; 2-tile KV stages ----------------
#define FPITCH 72
#define KH_OFF 0
#define VH_OFF (64 * FPITCH)
#define KV_STAGE_ELEMS (128 * FPITCH)
#define FLASH_SMEM (2 * KV_STAGE_ELEMS * 2)        // 36864 bytes
#define NQT (SEQ / 128)

__device__ __forceinline__ void flash_issue_kv(
    uint32_t sb, int stage,
    const __half* __restrict__ khi, const __half* __restrict__ vthi,
    int b, int hkv, int kt, int tid)
{
    #pragma unroll
    for (int it = 0; it < 4; it++) {
        int idx = tid + it * 256;
        int tile = idx >> 9;
        int r = (idx >> 3) & 63;
        int ch = idx & 7;
        const __half* src;
        int dstoff;
        if (tile == 0) { src = &khi[(((size_t)b * SEQ + kt * 64 + r) * HKV + hkv) * HD + ch * 8]; dstoff = KH_OFF; }
        else { src = &vthi[(((size_t)b * HKV + hkv) * HD + r) * SEQ + kt * 64 + ch * 8]; dstoff = VH_OFF; }
        uint32_t dst = sb + 2u * (uint32_t)(stage * KV_STAGE_ELEMS + dstoff + r * FPITCH + ch * 8);
        asm volatile("cp.async.cg.shared.global [%0], [%1], 16;" :: "r"(dst), "l"(src));
    }
    asm volatile("cp.async.commit_group;");
}

__global__ __launch_bounds__(256, 2) void flash_mma_kernel(
    const __half* __restrict__ qhi,
    const __half* __restrict__ khi, const __half* __restrict__ vthi,
    __half* __restrict__ outHi)
{
    extern __shared__ char smem[];
    const uint32_t sb = smem_to_u32(smem);
    __half* sm = (__half*)smem;

    const int tid = threadIdx.x;
    const int wid = tid >> 5;
    const int lid = tid & 31;
    const int g = lid >> 2;
    const int t4 = lid & 3;
    const int pairIdx = blockIdx.x;
    const int bh = blockIdx.y;
    const int b = bh >> 5;
    const int h = bh & 31;
    const int hkv = h >> 2;

    const int arow_l = (lid & 7) + ((lid >> 3) & 1) * 8;
    const int acol_l = (lid >> 4) * 8;
    const int brow_l = (lid & 7) + (lid >> 4) * 8;
    const int bcol_l = ((lid >> 3) & 1) * 8;

    const float scale = 0.125f;

    #pragma unroll
    for (int half = 0; half < 2; half++) {
        const int qt = half ? (NQT - 1 - pairIdx) : pairIdx;

        __syncthreads();
        #pragma unroll
        for (int it = 0; it < 4; it++) {
            int idx = tid + it * 256;
            int row = idx >> 3;
            int ch = idx & 7;
            size_t goff = (((size_t)b * SEQ + qt * 128 + row) * HQ + h) * HD + ch * 8;
            *(uint4*)&sm[row * FPITCH + ch * 8] = *(const uint4*)&qhi[goff];
        }
        __syncthreads();

        uint32_t qh[4][4];
        #pragma unroll
        for (int ks = 0; ks < 4; ks++) {
            uint32_t ad = sb + 2u * (uint32_t)((wid * 16 + arow_l) * FPITCH + ks * 16 + acol_l);
            LDM4(qh[ks][0], qh[ks][1], qh[ks][2], qh[ks][3], ad);
        }
        __syncthreads();

        float m0 = -1e30f, m1 = -1e30f, l0 = 0.f, l1 = 0.f;
        float oacc[8][4];
        #pragma unroll
        for (int nt = 0; nt < 8; nt++)
            #pragma unroll
            for (int r = 0; r < 4; r++) oacc[nt][r] = 0.f;

        const int row0 = qt * 128 + wid * 16;
        const int r_g = row0 + g;
        const int r_g8 = r_g + 8;
        const int nkt = 2 * qt + 2;

        flash_issue_kv(sb, 0, khi, vthi, b, hkv, 0, tid);

        for (int kt = 0; kt < nkt; kt++) {
            const int stg = kt & 1;
            if (kt + 1 < nkt) {
                flash_issue_kv(sb, 1 - stg, khi, vthi, b, hkv, kt + 1, tid);
                asm volatile("cp.async.wait_group 1;" ::: "memory");
            } else {
                asm volatile("cp.async.wait_group 0;" ::: "memory");
            }
            __syncthreads();

            const uint32_t kvb = sb + 2u * (uint32_t)(stg * KV_STAGE_ELEMS);

            float sacc[8][4];
            #pragma unroll
            for (int nt = 0; nt < 8; nt++)
                #pragma unroll
                for (int r = 0; r < 4; r++) sacc[nt][r] = 0.f;

            #pragma unroll
            for (int ks = 0; ks < 4; ks++) {
                uint32_t kf[4][4];
                #pragma unroll
                for (int ntp = 0; ntp < 4; ntp++) {
                    uint32_t bd = kvb + 2u * (uint32_t)(KH_OFF + (ntp * 16 + brow_l) * FPITCH + ks * 16 + bcol_l);
                    LDM4(kf[ntp][0], kf[ntp][1], kf[ntp][2], kf[ntp][3], bd);
                }
                #pragma unroll
                for (int ntp = 0; ntp < 4; ntp++) {
                    mma16816(sacc[2 * ntp],     qh[ks], kf[ntp][0], kf[ntp][1]);
                    mma16816(sacc[2 * ntp + 1], qh[ks], kf[ntp][2], kf[ntp][3]);
                }
            }

            const bool maybe_mask = (kt * 64 + 63 > row0);
            float mx0 = -1e30f, mx1 = -1e30f;
            #pragma unroll
            for (int nt = 0; nt < 8; nt++) {
                #pragma unroll
                for (int r = 0; r < 4; r++) sacc[nt][r] *= scale;
                if (maybe_mask) {
                    int colb = kt * 64 + nt * 8 + 2 * t4;
                    if (colb > r_g)      sacc[nt][0] = NEG_BIG;
                    if (colb + 1 > r_g)  sacc[nt][1] = NEG_BIG;
                    if (colb > r_g8)     sacc[nt][2] = NEG_BIG;
                    if (colb + 1 > r_g8) sacc[nt][3] = NEG_BIG;
                }
                mx0 = fmaxf(mx0, fmaxf(sacc[nt][0], sacc[nt][1]));
                mx1 = fmaxf(mx1, fmaxf(sacc[nt][2], sacc[nt][3]));
            }
            mx0 = fmaxf(mx0, __shfl_xor_sync(0xffffffffu, mx0, 1));
            mx0 = fmaxf(mx0, __shfl_xor_sync(0xffffffffu, mx0, 2));
            mx1 = fmaxf(mx1, __shfl_xor_sync(0xffffffffu, mx1, 1));
            mx1 = fmaxf(mx1, __shfl_xor_sync(0xffffffffu, mx1, 2));

            float mn0 = fmaxf(m0, mx0), mn1 = fmaxf(m1, mx1);
            float corr0 = __expf(m0 - mn0), corr1 = __expf(m1 - mn1);

            uint32_t ph[8][2];
            float rs0 = 0.f, rs1 = 0.f;
            #pragma unroll
            for (int nt = 0; nt < 8; nt++) {
                float p00 = __expf(sacc[nt][0] - mn0);
                float p01 = __expf(sacc[nt][1] - mn0);
                float p10 = __expf(sacc[nt][2] - mn1);
                float p11 = __expf(sacc[nt][3] - mn1);
                rs0 += p00 + p01;
                rs1 += p10 + p11;
                ph[nt][0] = pack_f16x2(p00, p01);
                ph[nt][1] = pack_f16x2(p10, p11);
            }
            rs0 += __shfl_xor_sync(0xffffffffu, rs0, 1);
            rs0 += __shfl_xor_sync(0xffffffffu, rs0, 2);
            rs1 += __shfl_xor_sync(0xffffffffu, rs1, 1);
            rs1 += __shfl_xor_sync(0xffffffffu, rs1, 2);

            l0 = l0 * corr0 + rs0;
            l1 = l1 * corr1 + rs1;
            m0 = mn0; m1 = mn1;
            #pragma unroll
            for (int nt = 0; nt < 8; nt++) {
                oacc[nt][0] *= corr0; oacc[nt][1] *= corr0;
                oacc[nt][2] *= corr1; oacc[nt][3] *= corr1;
            }

            #pragma unroll
            for (int ks = 0; ks < 4; ks++) {
                uint32_t pah[4] = { ph[2 * ks][0], ph[2 * ks][1], ph[2 * ks + 1][0], ph[2 * ks + 1][1] };
                uint32_t vfh[4][4];
                #pragma unroll
                for (int ntp = 0; ntp < 4; ntp++) {
                    uint32_t bd = kvb + 2u * (uint32_t)(VH_OFF + (ntp * 16 + brow_l) * FPITCH + ks * 16 + bcol_l);
                    LDM4(vfh[ntp][0], vfh[ntp][1], vfh[ntp][2], vfh[ntp][3], bd);
                }
                #pragma unroll
                for (int ntp = 0; ntp < 4; ntp++) {
                    mma16816(oacc[2 * ntp],     pah, vfh[ntp][0], vfh[ntp][1]);
                    mma16816(oacc[2 * ntp + 1], pah, vfh[ntp][2], vfh[ntp][3]);
                }
            }
            __syncthreads();
        }

        float inv0 = 1.0f / l0, inv1 = 1.0f / l1;
        uint32_t* oHi = (uint32_t*)outHi;
        #pragma unroll
        for (int nt = 0; nt < 8; nt++) {
            float o00 = oacc[nt][0] * inv0, o01 = oacc[nt][1] * inv0;
            float o10 = oacc[nt][2] * inv1, o11 = oacc[nt][3] * inv1;
            size_t row = (size_t)b * SEQ + qt * 128 + wid * 16 + g;
            int col = h * 64 + nt * 8 + 2 * t4;
            oHi[(row * 2048 + col) >> 1] = pack_f16x2(o00, o01);
            oHi[((row + 8) * 2048 + col) >> 1] = pack_f16x2(o10, o11);
        }
    }
}

// ---------------- launcher ----------------
extern "C" void kernel_launch(void* const* d_in, const int* in_sizes, int n_in,
                              void* d_out, int out_size)
{
    const float* hidden = (const float*)d_in[0];
    const float* Wq = (const float*)d_in[2];
    const float* Wk = (const float*)d_in[3];
    const float* Wv = (const float*)d_in[4];
    const float* Wo = (const float*)d_in[5];
    float* out = (float*)d_out;

    float* qkv_ptr;
    cudaGetSymbolAddress((void**)&qkv_ptr, g_qkv);

    __half *aHi, *bQKV, *bO;
    __half *qH, *kH, *vtH;
    cudaGetSymbolAddress((void**)&aHi, gA_hi);
    cudaGetSymbolAddress((void**)&bQKV, gBqkv);
    cudaGetSymbolAddress((void**)&bO, gBo);
    cudaGetSymbolAddress((void**)&qH, gQhi);
    cudaGetSymbolAddress((void**)&kH, gKhi);
    cudaGetSymbolAddress((void**)&vtH, gVThi);

    cudaFuncSetAttribute(gemm_fp16x1_kernel, cudaFuncAttributeMaxDynamicSharedMemorySize, GEMM1_SMEM);
    cudaFuncSetAttribute(flash_mma_kernel, cudaFuncAttributeMaxDynamicSharedMemorySize, FLASH_SMEM);

    // 1) fused input prep (A hi-only + all weight transposes)
    input_prep_kernel<<<IN_TOTAL_BLKS, 256>>>(hidden, Wq, Wk, Wv, Wo, aHi, bQKV, bO);

    // 2) fused QKV projection (single-A fp16)
    gemm_fp16x1_kernel<<<dim3(NQKV / 128, MROWS / 64), 128, GEMM1_SMEM>>>(aHi, bQKV, qkv_ptr, NQKV);

    // 3) fused prep (rope Q, rope K, V transpose)
    prep_kernel<<<PREP_TOTAL_BLKS, 256>>>(qkv_ptr, qH, kH, vtH);

    // 4) attention (single fp16 everywhere; writes fp16 output into aHi)
    {
        dim3 g(NQT / 2, BATCH * HQ);
        flash_mma_kernel<<<g, 256, FLASH_SMEM>>>(qH, kH, vtH, aHi);
    }

    // 5) output projection (single-A fp16)
    gemm_fp16x1_kernel<<<dim3(2048 / 128, MROWS / 64), 128, GEMM1_SMEM>>>(aHi, bO, out, 2048);
}